// round 5
// baseline (speedup 1.0000x reference)
#include <cuda_runtime.h>
#include <cuda_bf16.h>
#include <math.h>

#define Ldim 4096
#define Edim 512
#define Sdim 1024
#define Hdim 150
#define HP   160
#define MAXN 10
#define Ttot 40915
#define TP   40960

// ---------------------------------------------------------------------------
// Device scratch (zero-init at load; pad regions never written -> stay zero)
// ---------------------------------------------------------------------------
__device__ float g_A[Ldim * HP];
__device__ float g_B[Ldim * HP];
__device__ float g_C[Ldim * HP];
__device__ float g_H1[Ldim * HP];
__device__ float g_H2[Ldim * HP];
__device__ float g_attn[Ldim];
__device__ float g_X[TP * HP];
__device__ float g_sW3p[HP];
__device__ float g_sb2p[HP];

// Pre-split bf16 weights, layout [n][K3] (n-major, k' contiguous), K3 = 3*K.
// Slot pattern along k' (B side): [bh, bh, bl].
__device__ __align__(16) __nv_bfloat16 g_W1s[3 * 160 * 3072]; // states-GEMM: A|B|H1 tiles, K=1024
__device__ __align__(16) __nv_bfloat16 g_WCs[160 * 1536];     // embeds-GEMM, K=512
__device__ __align__(16) __nv_bfloat16 g_Wl2s[160 * 480];     // attn layer2, K=160
__device__ __align__(16) __nv_bfloat16 g_W2s[160 * 480];      // sm layer2,  K=160

// ---------------------------------------------------------------------------
// Weight split kernel: fp32 W[k][n] -> bf16 hi/lo triplets [n][3k+s]
// ---------------------------------------------------------------------------
__global__ void wsplit_kernel(const float* __restrict__ sW1,
                              const float* __restrict__ aW1,
                              const float* __restrict__ aW2,
                              const float* __restrict__ sW2,
                              const float* __restrict__ sW3,
                              const float* __restrict__ sb2)
{
    int idx = blockIdx.x * 256 + threadIdx.x;
    const int R1 = 3 * 160 * 1024;
    const int R2 = 160 * 512;
    const int R3 = 160 * 160;
    const int R4 = 160 * 160;

    if (idx < R1) {
        int t = idx / (160 * 1024);
        int r = idx % (160 * 1024);
        int n = r / 1024, kk = r % 1024;
        float v = 0.f;
        if (n < Hdim)
            v = (t == 0) ? sW1[kk * Hdim + n]
              : (t == 1) ? sW1[(1024 + kk) * Hdim + n]
                         : aW1[kk * Hdim + n];
        __nv_bfloat16 vh = __float2bfloat16(v);
        __nv_bfloat16 vl = __float2bfloat16(v - __bfloat162float(vh));
        size_t o = ((size_t)t * 160 + n) * 3072 + 3 * kk;
        g_W1s[o] = vh; g_W1s[o + 1] = vh; g_W1s[o + 2] = vl;
        return;
    }
    idx -= R1;
    if (idx < R2) {
        int n = idx / 512, kk = idx % 512;
        float v = (n < Hdim) ? sW1[(2048 + kk) * Hdim + n] : 0.f;
        __nv_bfloat16 vh = __float2bfloat16(v);
        __nv_bfloat16 vl = __float2bfloat16(v - __bfloat162float(vh));
        size_t o = (size_t)n * 1536 + 3 * kk;
        g_WCs[o] = vh; g_WCs[o + 1] = vh; g_WCs[o + 2] = vl;
        return;
    }
    idx -= R2;
    if (idx < R3) {
        int n = idx / 160, kk = idx % 160;
        float v = (n < Hdim && kk < Hdim) ? aW2[kk * Hdim + n] : 0.f;
        __nv_bfloat16 vh = __float2bfloat16(v);
        __nv_bfloat16 vl = __float2bfloat16(v - __bfloat162float(vh));
        size_t o = (size_t)n * 480 + 3 * kk;
        g_Wl2s[o] = vh; g_Wl2s[o + 1] = vh; g_Wl2s[o + 2] = vl;
        return;
    }
    idx -= R3;
    if (idx < R4) {
        int n = idx / 160, kk = idx % 160;
        float v = (n < Hdim && kk < Hdim) ? sW2[kk * Hdim + n] : 0.f;
        __nv_bfloat16 vh = __float2bfloat16(v);
        __nv_bfloat16 vl = __float2bfloat16(v - __bfloat162float(vh));
        size_t o = (size_t)n * 480 + 3 * kk;
        g_W2s[o] = vh; g_W2s[o + 1] = vh; g_W2s[o + 2] = vl;
        return;
    }
    idx -= R4;
    if (idx < HP) {
        g_sW3p[idx] = (idx < Hdim) ? sW3[idx] : 0.f;
        g_sb2p[idx] = (idx < Hdim) ? sb2[idx] : 0.f;
    }
}

// ---------------------------------------------------------------------------
// Unified tensor-core GEMM: dst = epi( X[f32] @ Wsplit + bias )
// BM=128, BN=160, 320 threads = 10 warps (2m x 5n), warp tile 64x32.
// mma.sync m16n8k16 bf16, hi/lo split via K'=3K.
// jobs: 0=states GEMM (grid.y 0..2 -> g_A/g_B/g_H1), 1=embeds->g_C,
//       2=H1@aW2->g_H2 (bias+relu), 3=X@sW2 fused layer3 -> out.
// ---------------------------------------------------------------------------
#define BM  128
#define AST 56   // bf16 stride (28 words): 8 frag rows hit 8 distinct bank groups
#define BST 56

__global__ __launch_bounds__(320, 2)
void mma_gemm_kernel(int job,
                     const float* __restrict__ Xarg,
                     const float* __restrict__ bias_arg,
                     const float* __restrict__ sb3,
                     float* __restrict__ outv)
{
    __shared__ __align__(16) __nv_bfloat16 A_s[BM * AST];
    __shared__ __align__(16) __nv_bfloat16 B_s[160 * BST];
    __shared__ float red[BM * 5];

    // job config
    const float* X; int lda, nchunks, mode;
    const __nv_bfloat16* W;
    const float* bias = bias_arg;
    float* dst = nullptr;
    if (job == 0) {
        int y = blockIdx.y;
        X = Xarg; lda = Sdim; nchunks = 64;
        W = g_W1s + (size_t)y * 160 * 3072;
        dst = (y == 0) ? g_A : (y == 1) ? g_B : g_H1;
        mode = (y == 2) ? 1 : 0;
    } else if (job == 1) {
        X = Xarg; lda = Edim; nchunks = 32; W = g_WCs; dst = g_C; mode = 0;
    } else if (job == 2) {
        X = g_H1; lda = HP; nchunks = 10; W = g_Wl2s; dst = g_H2; mode = 1;
    } else {
        X = g_X; lda = HP; nchunks = 10; W = g_W2s; mode = 2;
    }
    const int Krow = nchunks * 48;

    const int tid  = threadIdx.x;
    const int lane = tid & 31;
    const int w    = tid >> 5;      // 0..9
    const int wm   = w / 5;         // 0..1
    const int wn   = w % 5;         // 0..4
    const int g    = lane >> 2;     // 0..7
    const int tg   = lane & 3;      // 0..3
    const int row0 = blockIdx.x * BM;

    float acc[4][4][4];
#pragma unroll
    for (int i = 0; i < 4; i++)
#pragma unroll
        for (int j = 0; j < 4; j++)
#pragma unroll
            for (int k = 0; k < 4; k++) acc[i][j][k] = 0.f;

    const unsigned* As32 = (const unsigned*)A_s;
    const unsigned* Bs32 = (const unsigned*)B_s;
    const int abase = (wm * 64 + g) * 28 + tg;
    const int bbase = (wn * 32 + g) * 28 + tg;

    for (int ch = 0; ch < nchunks; ch++) {
        // --- stage A: 128 rows x 16 k fp32 -> hi/lo triplets ---
        for (int idx = tid; idx < BM * 4; idx += 320) {
            int m = idx >> 2, kq = idx & 3;
            float4 xv = *(const float4*)(X + (size_t)(row0 + m) * lda + ch * 16 + kq * 4);
            int base = m * AST + 12 * kq;
            float e[4] = {xv.x, xv.y, xv.z, xv.w};
#pragma unroll
            for (int q = 0; q < 4; q++) {
                __nv_bfloat16 xh = __float2bfloat16(e[q]);
                __nv_bfloat16 xl = __float2bfloat16(e[q] - __bfloat162float(xh));
                A_s[base + 3 * q + 0] = xh;
                A_s[base + 3 * q + 1] = xl;
                A_s[base + 3 * q + 2] = xh;
            }
        }
        // --- stage B: 160 rows x 48 bf16, contiguous in global ---
        for (int idx = tid; idx < 960; idx += 320) {
            int n = idx / 6, q = idx % 6;
            *(uint4*)(B_s + n * BST + q * 8) =
                *(const uint4*)(W + (size_t)n * Krow + ch * 48 + q * 8);
        }
        __syncthreads();

#pragma unroll
        for (int st = 0; st < 3; st++) {
            const int ko = st * 8;
            unsigned b0[4], b1[4];
#pragma unroll
            for (int j = 0; j < 4; j++) {
                b0[j] = Bs32[bbase + j * 224 + ko];
                b1[j] = Bs32[bbase + j * 224 + ko + 4];
            }
#pragma unroll
            for (int i = 0; i < 4; i++) {
                unsigned a0 = As32[abase + i * 448 + ko];
                unsigned a1 = As32[abase + i * 448 + 224 + ko];
                unsigned a2 = As32[abase + i * 448 + ko + 4];
                unsigned a3 = As32[abase + i * 448 + 224 + ko + 4];
#pragma unroll
                for (int j = 0; j < 4; j++) {
                    asm volatile(
                        "mma.sync.aligned.m16n8k16.row.col.f32.bf16.bf16.f32 "
                        "{%0,%1,%2,%3},{%4,%5,%6,%7},{%8,%9},{%0,%1,%2,%3};"
                        : "+f"(acc[i][j][0]), "+f"(acc[i][j][1]),
                          "+f"(acc[i][j][2]), "+f"(acc[i][j][3])
                        : "r"(a0), "r"(a1), "r"(a2), "r"(a3),
                          "r"(b0[j]), "r"(b1[j]));
                }
            }
        }
        __syncthreads();
    }

    if (mode != 2) {
#pragma unroll
        for (int i = 0; i < 4; i++) {
            int r = row0 + wm * 64 + i * 16 + g;
#pragma unroll
            for (int j = 0; j < 4; j++) {
                int c = wn * 32 + j * 8 + 2 * tg;
                if (c < Hdim) {
                    float v0 = acc[i][j][0], v1 = acc[i][j][1];
                    float v2 = acc[i][j][2], v3 = acc[i][j][3];
                    if (mode == 1) {
                        float bc = bias[c], bc1 = bias[c + 1];
                        v0 = fmaxf(v0 + bc, 0.f);  v1 = fmaxf(v1 + bc1, 0.f);
                        v2 = fmaxf(v2 + bc, 0.f);  v3 = fmaxf(v3 + bc1, 0.f);
                    }
                    dst[(size_t)r * HP + c]           = v0;
                    dst[(size_t)r * HP + c + 1]       = v1;
                    dst[(size_t)(r + 8) * HP + c]     = v2;
                    dst[(size_t)(r + 8) * HP + c + 1] = v3;
                }
            }
        }
    } else {
#pragma unroll
        for (int i = 0; i < 4; i++) {
            float pl = 0.f, ph = 0.f;
#pragma unroll
            for (int j = 0; j < 4; j++) {
                int c = wn * 32 + j * 8 + 2 * tg;
                float w0 = g_sW3p[c], w1 = g_sW3p[c + 1];
                float s0 = g_sb2p[c], s1 = g_sb2p[c + 1];
                pl += w0 * fmaxf(acc[i][j][0] + s0, 0.f)
                    + w1 * fmaxf(acc[i][j][1] + s1, 0.f);
                ph += w0 * fmaxf(acc[i][j][2] + s0, 0.f)
                    + w1 * fmaxf(acc[i][j][3] + s1, 0.f);
            }
            pl += __shfl_xor_sync(0xffffffffu, pl, 1);
            pl += __shfl_xor_sync(0xffffffffu, pl, 2);
            ph += __shfl_xor_sync(0xffffffffu, ph, 1);
            ph += __shfl_xor_sync(0xffffffffu, ph, 2);
            if (tg == 0) {
                red[(wm * 64 + i * 16 + g) * 5 + wn]     = pl;
                red[(wm * 64 + i * 16 + g + 8) * 5 + wn] = ph;
            }
        }
        __syncthreads();
        if (tid < BM) {
            float s = sb3[0];
#pragma unroll
            for (int q = 0; q < 5; q++) s += red[tid * 5 + q];
            int t = row0 + tid;
            if (t < Ttot) outv[t] = s;
        }
    }
}

// ---------------------------------------------------------------------------
// attn layer 3: g_attn[m] = g_H2[m] . aW3 + ab3
// ---------------------------------------------------------------------------
__global__ void attn_l3_kernel(const float* __restrict__ aW3,
                               const float* __restrict__ ab3)
{
    int lane = threadIdx.x & 31;
    int m = blockIdx.x * 4 + (threadIdx.x >> 5);
    float acc = 0.f;
#pragma unroll
    for (int i = 0; i < 5; i++) {
        int c = lane + 32 * i;
        float w = (c < Hdim) ? aW3[c] : 0.f;
        acc += g_H2[(size_t)m * HP + c] * w;
    }
#pragma unroll
    for (int o = 16; o > 0; o >>= 1) acc += __shfl_xor_sync(0xffffffffu, acc, o);
    if (lane == 0) g_attn[m] = acc + ab3[0];
}

// ---------------------------------------------------------------------------
// Pool kernel: X[t] = relu(A[s] + B[s+n-1] + softmax(attn win).C + sb1)
// ---------------------------------------------------------------------------
__global__ void pool_kernel(const float* __restrict__ sb1)
{
    __shared__ float attw[140];
    __shared__ float wsm[128 * 12];

    const int tid = threadIdx.x;
    const int n   = blockIdx.y + 1;
    const int s0  = blockIdx.x * 128;
    const int M   = Ldim - n + 1;
    const int nw  = 128 + n - 1;
    const int off = (n - 1) * (Ldim + 1) - (n * (n - 1)) / 2;

    for (int idx = tid; idx < nw; idx += 256) {
        int gg = s0 + idx;
        attw[idx] = (gg < Ldim) ? g_attn[gg] : 0.f;
    }
    __syncthreads();

    if (tid < 128) {
        int r = tid;
        float mx = -1e30f;
        for (int j = 0; j < n; j++) mx = fmaxf(mx, attw[r + j]);
        float s = 0.f;
        for (int j = 0; j < n; j++) {
            float e = expf(attw[r + j] - mx);
            wsm[r * 12 + j] = e;
            s += e;
        }
        float inv = 1.f / s;
        for (int j = 0; j < n; j++) wsm[r * 12 + j] *= inv;
    }
    __syncthreads();

    const int warp = tid >> 5, lane = tid & 31;
    for (int r = warp; r < 128; r += 8) {
        int start = s0 + r;
        if (start >= M) continue;
        float wj[MAXN];
        for (int j = 0; j < n; j++) wj[j] = wsm[r * 12 + j];
        size_t tb = (size_t)(off + start) * HP;
        size_t ab = (size_t)start * HP;
        size_t bb = (size_t)(start + n - 1) * HP;
#pragma unroll
        for (int k = 0; k < 5; k++) {
            int c = lane + 32 * k;
            float v = 0.f;
            if (c < Hdim) {
                v = g_A[ab + c] + g_B[bb + c] + sb1[c];
                for (int j = 0; j < n; j++)
                    v += wj[j] * g_C[(size_t)(start + j) * HP + c];
                v = fmaxf(v, 0.f);
            }
            g_X[tb + c] = v;
        }
    }
}

// ---------------------------------------------------------------------------
extern "C" void kernel_launch(void* const* d_in, const int* in_sizes, int n_in,
                              void* d_out, int out_size)
{
    const float* embeds = (const float*)d_in[0];
    const float* states = (const float*)d_in[1];
    const float* aW1    = (const float*)d_in[2];
    const float* ab1    = (const float*)d_in[3];
    const float* aW2    = (const float*)d_in[4];
    const float* ab2    = (const float*)d_in[5];
    const float* aW3    = (const float*)d_in[6];
    const float* ab3    = (const float*)d_in[7];
    const float* sW1    = (const float*)d_in[8];
    const float* sb1    = (const float*)d_in[9];
    const float* sW2    = (const float*)d_in[10];
    const float* sb2    = (const float*)d_in[11];
    const float* sW3    = (const float*)d_in[12];
    const float* sb3    = (const float*)d_in[13];
    float* out = (float*)d_out;

    // weight splits + padded sW3/sb2
    wsplit_kernel<<<2441, 256>>>(sW1, aW1, aW2, sW2, sW3, sb2);
    // states @ [sW1_a | sW1_b | aW1]  ->  g_A, g_B, g_H1
    mma_gemm_kernel<<<dim3(Ldim / BM, 3), 320>>>(0, states, ab1, nullptr, nullptr);
    // embeds @ sW1_e -> g_C
    mma_gemm_kernel<<<dim3(Ldim / BM, 1), 320>>>(1, embeds, nullptr, nullptr, nullptr);
    // attn layer2: g_H1 @ aW2 -> g_H2
    mma_gemm_kernel<<<dim3(Ldim / BM, 1), 320>>>(2, nullptr, ab2, nullptr, nullptr);
    // attn layer3 -> g_attn
    attn_l3_kernel<<<Ldim / 4, 128>>>(aW3, ab3);
    // pooled h1 rows for all (n, start) -> g_X
    pool_kernel<<<dim3(32, 10), 256>>>(sb1);
    // big GEMM + fused layer3 -> out
    mma_gemm_kernel<<<dim3(TP / BM, 1), 320>>>(3, nullptr, nullptr, sb3, out);
}

// round 6
// speedup vs baseline: 1.4424x; 1.4424x over previous
#include <cuda_runtime.h>
#include <cuda_bf16.h>
#include <math.h>

#define Ldim 4096
#define Edim 512
#define Sdim 1024
#define Hdim 150
#define HP   160
#define MAXN 10
#define Ttot 40915
#define TP   40960
#define BM   128
#define SMX  67072   // dynamic smem bytes for mma kernel

// ---------------------------------------------------------------------------
// Device scratch (zero-init; pad regions never written -> stay zero)
// ---------------------------------------------------------------------------
__device__ float g_A[Ldim * HP];
__device__ float g_B[Ldim * HP];
__device__ float g_C[Ldim * HP];
__device__ float g_H2[Ldim * HP];
__device__ float g_attn[Ldim];
__device__ float g_sW3p[HP];
__device__ float g_sb2p[HP];

// bf16 hi/lo triplet buffers.  A-side slot pattern: [xh, xl, xh]
//                              B-side slot pattern: [bh, bh, bl]
__device__ __align__(16) __nv_bfloat16 g_Ss[(size_t)Ldim * 3072];   // states
__device__ __align__(16) __nv_bfloat16 g_Es[(size_t)Ldim * 1536];   // embeds
__device__ __align__(16) __nv_bfloat16 g_H1s[(size_t)Ldim * 480];   // attn h1
__device__ __align__(16) __nv_bfloat16 g_Xs[(size_t)TP * 480];      // pooled rows
__device__ __align__(16) __nv_bfloat16 g_W1s[3 * 160 * 3072];
__device__ __align__(16) __nv_bfloat16 g_WCs[160 * 1536];
__device__ __align__(16) __nv_bfloat16 g_Wl2s[160 * 480];
__device__ __align__(16) __nv_bfloat16 g_W2s[160 * 480];

// ---------------------------------------------------------------------------
// Activation split: fp32 -> A-side triplets, contiguous & coalesced
// ---------------------------------------------------------------------------
__global__ void split_acts(const float* __restrict__ states,
                           const float* __restrict__ embeds)
{
    int idx = blockIdx.x * 256 + threadIdx.x;
    const int NS = Ldim * 128;              // state k-groups (K=1024 -> 128)
    const float* src;
    __nv_bfloat16* dst;
    int kg;
    if (idx < NS) {
        int row = idx >> 7; kg = idx & 127;
        src = states + (size_t)row * Sdim;
        dst = g_Ss + (size_t)row * 3072;
    } else {
        idx -= NS;
        int row = idx >> 6; kg = idx & 63;
        src = embeds + (size_t)row * Edim;
        dst = g_Es + (size_t)row * 1536;
    }
    float4 v0 = *(const float4*)(src + kg * 8);
    float4 v1 = *(const float4*)(src + kg * 8 + 4);
    float e[8] = {v0.x, v0.y, v0.z, v0.w, v1.x, v1.y, v1.z, v1.w};
    __align__(16) __nv_bfloat16 t[24];
#pragma unroll
    for (int q = 0; q < 8; q++) {
        __nv_bfloat16 h = __float2bfloat16(e[q]);
        __nv_bfloat16 l = __float2bfloat16(e[q] - __bfloat162float(h));
        t[3 * q] = h; t[3 * q + 1] = l; t[3 * q + 2] = h;
    }
    uint4* d4 = (uint4*)(dst + kg * 24);
    const uint4* s4 = (const uint4*)t;
    d4[0] = s4[0]; d4[1] = s4[1]; d4[2] = s4[2];
}

// ---------------------------------------------------------------------------
// Weight split: fp32 W[k][n] -> B-side triplets, [n][3k] layout
// ---------------------------------------------------------------------------
__global__ void split_w(const float* __restrict__ sW1,
                        const float* __restrict__ aW1,
                        const float* __restrict__ aW2,
                        const float* __restrict__ sW2,
                        const float* __restrict__ sW3,
                        const float* __restrict__ sb2)
{
    int idx = blockIdx.x * 256 + threadIdx.x;
    float e[8];
    __nv_bfloat16* dst;

    if (idx < 61440) {                       // g_W1s: 3 tiles, K=1024
        int t = idx / 20480, r = idx % 20480;
        int kg = r / 160, n = r % 160;
#pragma unroll
        for (int q = 0; q < 8; q++) {
            int k = kg * 8 + q;
            float v = 0.f;
            if (n < Hdim)
                v = (t == 0) ? sW1[(size_t)k * Hdim + n]
                  : (t == 1) ? sW1[(size_t)(1024 + k) * Hdim + n]
                             : aW1[(size_t)k * Hdim + n];
            e[q] = v;
        }
        dst = g_W1s + ((size_t)t * 160 + n) * 3072 + kg * 24;
    } else if (idx < 71680) {                // g_WCs: K=512
        int r = idx - 61440;
        int kg = r / 160, n = r % 160;
#pragma unroll
        for (int q = 0; q < 8; q++) {
            int k = kg * 8 + q;
            e[q] = (n < Hdim) ? sW1[(size_t)(2048 + k) * Hdim + n] : 0.f;
        }
        dst = g_WCs + (size_t)n * 1536 + kg * 24;
    } else if (idx < 74880) {                // g_Wl2s: K=160 (150 real)
        int r = idx - 71680;
        int kg = r / 160, n = r % 160;
#pragma unroll
        for (int q = 0; q < 8; q++) {
            int k = kg * 8 + q;
            e[q] = (n < Hdim && k < Hdim) ? aW2[(size_t)k * Hdim + n] : 0.f;
        }
        dst = g_Wl2s + (size_t)n * 480 + kg * 24;
    } else if (idx < 78080) {                // g_W2s
        int r = idx - 74880;
        int kg = r / 160, n = r % 160;
#pragma unroll
        for (int q = 0; q < 8; q++) {
            int k = kg * 8 + q;
            e[q] = (n < Hdim && k < Hdim) ? sW2[(size_t)k * Hdim + n] : 0.f;
        }
        dst = g_W2s + (size_t)n * 480 + kg * 24;
    } else if (idx < 78240) {
        int c = idx - 78080;
        g_sW3p[c] = (c < Hdim) ? sW3[c] : 0.f;
        g_sb2p[c] = (c < Hdim) ? sb2[c] : 0.f;
        return;
    } else return;

    __align__(16) __nv_bfloat16 t24[24];
#pragma unroll
    for (int q = 0; q < 8; q++) {
        __nv_bfloat16 h = __float2bfloat16(e[q]);
        __nv_bfloat16 l = __float2bfloat16(e[q] - __bfloat162float(h));
        t24[3 * q] = h; t24[3 * q + 1] = h; t24[3 * q + 2] = l;
    }
    uint4* d4 = (uint4*)dst;
    const uint4* s4 = (const uint4*)t24;
    d4[0] = s4[0]; d4[1] = s4[1]; d4[2] = s4[2];
}

// ---------------------------------------------------------------------------
// Tensor-core GEMM, double-buffered. BM=128, BN=160, BK'=48.
// 320 threads = 10 warps (2m x 5n), warp tile 64x32. mma m16n8k16 bf16.
// mode: 0 = fp32 store, 1 = bias+relu fp32, 2 = fused layer3 -> out,
//       3 = bias+relu -> bf16 triplet store (A-side pattern)
// ---------------------------------------------------------------------------
__device__ __forceinline__ void do_mma(const unsigned* As32, const unsigned* Bs32,
                                       int abase, int bbase, float acc[4][4][4])
{
#pragma unroll
    for (int st = 0; st < 3; st++) {
        const int ko = st * 8;
        unsigned b0[4], b1[4];
#pragma unroll
        for (int j = 0; j < 4; j++) {
            b0[j] = Bs32[bbase + j * 224 + ko];
            b1[j] = Bs32[bbase + j * 224 + ko + 4];
        }
#pragma unroll
        for (int i = 0; i < 4; i++) {
            unsigned a0 = As32[abase + i * 448 + ko];
            unsigned a1 = As32[abase + i * 448 + 224 + ko];
            unsigned a2 = As32[abase + i * 448 + ko + 4];
            unsigned a3 = As32[abase + i * 448 + 224 + ko + 4];
#pragma unroll
            for (int j = 0; j < 4; j++) {
                asm volatile(
                    "mma.sync.aligned.m16n8k16.row.col.f32.bf16.bf16.f32 "
                    "{%0,%1,%2,%3},{%4,%5,%6,%7},{%8,%9},{%0,%1,%2,%3};"
                    : "+f"(acc[i][j][0]), "+f"(acc[i][j][1]),
                      "+f"(acc[i][j][2]), "+f"(acc[i][j][3])
                    : "r"(a0), "r"(a1), "r"(a2), "r"(a3),
                      "r"(b0[j]), "r"(b1[j]));
            }
        }
    }
}

#define LOAD_AB(ch) do {                                                      \
    int c48 = (ch) * 48;                                                      \
    _Pragma("unroll")                                                         \
    for (int it = 0; it < 3; it++) {                                          \
        int idx = tid + it * 320;                                             \
        if (it < 2 || tid < 128) {                                            \
            int m = idx / 6, q = idx - 6 * m;                                 \
            rA[it] = *(const uint4*)(Asrc + (size_t)(row0 + m) * Kp + c48 + q * 8); \
        }                                                                     \
    }                                                                         \
    _Pragma("unroll")                                                         \
    for (int it = 0; it < 3; it++) {                                          \
        int idx = tid + it * 320;                                             \
        int n = idx / 6, q = idx - 6 * n;                                     \
        rB[it] = *(const uint4*)(Wsrc + (size_t)n * Kp + c48 + q * 8);        \
    }                                                                         \
} while (0)

#define STORE_AB(pp) do {                                                     \
    _Pragma("unroll")                                                         \
    for (int it = 0; it < 3; it++) {                                          \
        int idx = tid + it * 320;                                             \
        if (it < 2 || tid < 128) {                                            \
            int m = idx / 6, q = idx - 6 * m;                                 \
            *(uint4*)(Abuf[pp] + m * 56 + q * 8) = rA[it];                    \
        }                                                                     \
    }                                                                         \
    _Pragma("unroll")                                                         \
    for (int it = 0; it < 3; it++) {                                          \
        int idx = tid + it * 320;                                             \
        int n = idx / 6, q = idx - 6 * n;                                     \
        *(uint4*)(Bbuf[pp] + n * 56 + q * 8) = rB[it];                        \
    }                                                                         \
} while (0)

__global__ __launch_bounds__(320)
void mma_gemm_kernel(int job,
                     const float* __restrict__ bias,
                     const float* __restrict__ sb3,
                     float* __restrict__ outv)
{
    extern __shared__ char smx[];
    __nv_bfloat16* Abuf[2] = {(__nv_bfloat16*)smx, (__nv_bfloat16*)smx + 7168};
    __nv_bfloat16* Bbuf[2] = {(__nv_bfloat16*)smx + 14336,
                              (__nv_bfloat16*)smx + 23296};
    float* red = (float*)(smx + 64512);

    // job config
    const __nv_bfloat16 *Asrc, *Wsrc;
    int Kp, nch, mode;
    float* dst = nullptr;
    if (job == 0) {
        int y = blockIdx.y;
        if (y < 3) {
            Asrc = g_Ss; Kp = 3072; nch = 64;
            Wsrc = g_W1s + (size_t)y * 160 * 3072;
            if (y == 0)      { dst = g_A; mode = 0; }
            else if (y == 1) { dst = g_B; mode = 0; }
            else             { mode = 3; }
        } else {
            Asrc = g_Es; Kp = 1536; nch = 32; Wsrc = g_WCs; dst = g_C; mode = 0;
        }
    } else if (job == 2) {
        Asrc = g_H1s; Kp = 480; nch = 10; Wsrc = g_Wl2s; dst = g_H2; mode = 1;
    } else {
        Asrc = g_Xs; Kp = 480; nch = 10; Wsrc = g_W2s; mode = 2;
    }

    const int tid  = threadIdx.x;
    const int lane = tid & 31;
    const int w    = tid >> 5;
    const int wm   = w / 5;
    const int wn   = w % 5;
    const int g    = lane >> 2;
    const int tg   = lane & 3;
    const int row0 = blockIdx.x * BM;
    const int abase = (wm * 64 + g) * 28 + tg;
    const int bbase = (wn * 32 + g) * 28 + tg;

    float acc[4][4][4];
#pragma unroll
    for (int i = 0; i < 4; i++)
#pragma unroll
        for (int j = 0; j < 4; j++)
#pragma unroll
            for (int k = 0; k < 4; k++) acc[i][j][k] = 0.f;

    uint4 rA[3], rB[3];

    LOAD_AB(0);
    STORE_AB(0);
    __syncthreads();
    int p = 0;
    for (int ch = 0; ch < nch; ch++) {
        bool more = (ch + 1 < nch);
        if (more) LOAD_AB(ch + 1);
        do_mma((const unsigned*)Abuf[p], (const unsigned*)Bbuf[p], abase, bbase, acc);
        __syncthreads();
        if (more) { STORE_AB(p ^ 1); __syncthreads(); }
        p ^= 1;
    }

    if (mode == 0 || mode == 1) {
#pragma unroll
        for (int i = 0; i < 4; i++) {
            int r = row0 + wm * 64 + i * 16 + g;
#pragma unroll
            for (int j = 0; j < 4; j++) {
                int c = wn * 32 + j * 8 + 2 * tg;
                if (c < Hdim) {
                    float v0 = acc[i][j][0], v1 = acc[i][j][1];
                    float v2 = acc[i][j][2], v3 = acc[i][j][3];
                    if (mode == 1) {
                        float b0 = bias[c], b1 = bias[c + 1];
                        v0 = fmaxf(v0 + b0, 0.f); v1 = fmaxf(v1 + b1, 0.f);
                        v2 = fmaxf(v2 + b0, 0.f); v3 = fmaxf(v3 + b1, 0.f);
                    }
                    dst[(size_t)r * HP + c]           = v0;
                    dst[(size_t)r * HP + c + 1]       = v1;
                    dst[(size_t)(r + 8) * HP + c]     = v2;
                    dst[(size_t)(r + 8) * HP + c + 1] = v3;
                }
            }
        }
    } else if (mode == 3) {
#pragma unroll
        for (int i = 0; i < 4; i++) {
            int r = row0 + wm * 64 + i * 16 + g;
#pragma unroll
            for (int j = 0; j < 4; j++) {
                int c = wn * 32 + j * 8 + 2 * tg;
                if (c < Hdim) {
                    float b0 = bias[c], b1 = bias[c + 1];
                    float v0 = fmaxf(acc[i][j][0] + b0, 0.f);
                    float v1 = fmaxf(acc[i][j][1] + b1, 0.f);
                    float v2 = fmaxf(acc[i][j][2] + b0, 0.f);
                    float v3 = fmaxf(acc[i][j][3] + b1, 0.f);
#pragma unroll
                    for (int hh = 0; hh < 2; hh++) {
                        float va = hh ? v2 : v0, vb = hh ? v3 : v1;
                        int rr = r + 8 * hh;
                        __nv_bfloat16 ha = __float2bfloat16(va);
                        __nv_bfloat16 la = __float2bfloat16(va - __bfloat162float(ha));
                        __nv_bfloat16 hb = __float2bfloat16(vb);
                        __nv_bfloat16 lb = __float2bfloat16(vb - __bfloat162float(hb));
                        __nv_bfloat162* pt =
                            (__nv_bfloat162*)(g_H1s + (size_t)rr * 480 + 3 * c);
                        pt[0] = __nv_bfloat162{ha, la};
                        pt[1] = __nv_bfloat162{ha, hb};
                        pt[2] = __nv_bfloat162{lb, hb};
                    }
                }
            }
        }
    } else {
#pragma unroll
        for (int i = 0; i < 4; i++) {
            float pl = 0.f, ph = 0.f;
#pragma unroll
            for (int j = 0; j < 4; j++) {
                int c = wn * 32 + j * 8 + 2 * tg;
                float w0 = g_sW3p[c], w1 = g_sW3p[c + 1];
                float s0 = g_sb2p[c], s1 = g_sb2p[c + 1];
                pl += w0 * fmaxf(acc[i][j][0] + s0, 0.f)
                    + w1 * fmaxf(acc[i][j][1] + s1, 0.f);
                ph += w0 * fmaxf(acc[i][j][2] + s0, 0.f)
                    + w1 * fmaxf(acc[i][j][3] + s1, 0.f);
            }
            pl += __shfl_xor_sync(0xffffffffu, pl, 1);
            pl += __shfl_xor_sync(0xffffffffu, pl, 2);
            ph += __shfl_xor_sync(0xffffffffu, ph, 1);
            ph += __shfl_xor_sync(0xffffffffu, ph, 2);
            if (tg == 0) {
                red[(wm * 64 + i * 16 + g) * 5 + wn]     = pl;
                red[(wm * 64 + i * 16 + g + 8) * 5 + wn] = ph;
            }
        }
        __syncthreads();
        if (tid < BM) {
            float s = sb3[0];
#pragma unroll
            for (int q = 0; q < 5; q++) s += red[tid * 5 + q];
            int t = row0 + tid;
            if (t < Ttot) outv[t] = s;
        }
    }
}

// ---------------------------------------------------------------------------
// attn layer 3
// ---------------------------------------------------------------------------
__global__ void attn_l3_kernel(const float* __restrict__ aW3,
                               const float* __restrict__ ab3)
{
    int lane = threadIdx.x & 31;
    int m = blockIdx.x * 4 + (threadIdx.x >> 5);
    float acc = 0.f;
#pragma unroll
    for (int i = 0; i < 5; i++) {
        int c = lane + 32 * i;
        float w = (c < Hdim) ? aW3[c] : 0.f;
        acc += g_H2[(size_t)m * HP + c] * w;
    }
#pragma unroll
    for (int o = 16; o > 0; o >>= 1) acc += __shfl_xor_sync(0xffffffffu, acc, o);
    if (lane == 0) g_attn[m] = acc + ab3[0];
}

// ---------------------------------------------------------------------------
// Pool kernel: writes bf16 triplets directly into g_Xs
// ---------------------------------------------------------------------------
__global__ void pool_kernel(const float* __restrict__ sb1)
{
    __shared__ float attw[140];
    __shared__ float wsm[128 * 12];

    const int tid = threadIdx.x;
    const int n   = blockIdx.y + 1;
    const int s0  = blockIdx.x * 128;
    const int M   = Ldim - n + 1;
    const int nw  = 128 + n - 1;
    const int off = (n - 1) * (Ldim + 1) - (n * (n - 1)) / 2;

    for (int idx = tid; idx < nw; idx += 256) {
        int gg = s0 + idx;
        attw[idx] = (gg < Ldim) ? g_attn[gg] : 0.f;
    }
    __syncthreads();

    if (tid < 128) {
        int r = tid;
        float mx = -1e30f;
        for (int j = 0; j < n; j++) mx = fmaxf(mx, attw[r + j]);
        float s = 0.f;
        for (int j = 0; j < n; j++) {
            float e = expf(attw[r + j] - mx);
            wsm[r * 12 + j] = e;
            s += e;
        }
        float inv = 1.f / s;
        for (int j = 0; j < n; j++) wsm[r * 12 + j] *= inv;
    }
    __syncthreads();

    const int warp = tid >> 5, lane = tid & 31;
    for (int r = warp; r < 128; r += 8) {
        int start = s0 + r;
        if (start >= M) continue;
        float wj[MAXN];
        for (int j = 0; j < n; j++) wj[j] = wsm[r * 12 + j];
        size_t tb = (size_t)(off + start) * 480;
        size_t ab = (size_t)start * HP;
        size_t bb = (size_t)(start + n - 1) * HP;
#pragma unroll
        for (int k = 0; k < 5; k++) {
            int c = lane + 32 * k;
            if (c < Hdim) {
                float v = g_A[ab + c] + g_B[bb + c] + sb1[c];
                for (int j = 0; j < n; j++)
                    v += wj[j] * g_C[(size_t)(start + j) * HP + c];
                v = fmaxf(v, 0.f);
                __nv_bfloat16 h = __float2bfloat16(v);
                __nv_bfloat16 l = __float2bfloat16(v - __bfloat162float(h));
                g_Xs[tb + 3 * c]     = h;
                g_Xs[tb + 3 * c + 1] = l;
                g_Xs[tb + 3 * c + 2] = h;
            }
        }
    }
}

// ---------------------------------------------------------------------------
extern "C" void kernel_launch(void* const* d_in, const int* in_sizes, int n_in,
                              void* d_out, int out_size)
{
    const float* embeds = (const float*)d_in[0];
    const float* states = (const float*)d_in[1];
    const float* aW1    = (const float*)d_in[2];
    const float* ab1    = (const float*)d_in[3];
    const float* aW2    = (const float*)d_in[4];
    const float* ab2    = (const float*)d_in[5];
    const float* aW3    = (const float*)d_in[6];
    const float* ab3    = (const float*)d_in[7];
    const float* sW1    = (const float*)d_in[8];
    const float* sb1    = (const float*)d_in[9];
    const float* sW2    = (const float*)d_in[10];
    const float* sb2    = (const float*)d_in[11];
    const float* sW3    = (const float*)d_in[12];
    const float* sb3    = (const float*)d_in[13];
    float* out = (float*)d_out;

    cudaFuncSetAttribute(mma_gemm_kernel,
                         cudaFuncAttributeMaxDynamicSharedMemorySize, SMX);

    // bf16 triplet splits
    split_acts<<<3072, 256>>>(states, embeds);
    split_w<<<306, 256>>>(sW1, aW1, aW2, sW2, sW3, sb2);
    // merged precompute GEMMs: g_A, g_B, H1-triplets, g_C  (one wave)
    mma_gemm_kernel<<<dim3(Ldim / BM, 4), 320, SMX>>>(0, ab1, nullptr, nullptr);
    // attn layer2: H1 @ aW2 -> g_H2
    mma_gemm_kernel<<<dim3(Ldim / BM, 1), 320, SMX>>>(2, ab2, nullptr, nullptr);
    // attn layer3 -> g_attn
    attn_l3_kernel<<<Ldim / 4, 128>>>(aW3, ab3);
    // pooled rows (bf16 triplets) -> g_Xs
    pool_kernel<<<dim3(32, 10), 256>>>(sb1);
    // big GEMM + fused layer3 -> out
    mma_gemm_kernel<<<dim3(TP / BM, 1), 320, SMX>>>(3, nullptr, sb3, out);
}

// round 7
// speedup vs baseline: 1.6443x; 1.1400x over previous
#include <cuda_runtime.h>
#include <cuda_bf16.h>
#include <math.h>

#define Ldim 4096
#define Edim 512
#define Sdim 1024
#define Hdim 150
#define HP   160
#define MAXN 10
#define Ttot 40915
#define TP   40960

// ---------------------------------------------------------------------------
// Device scratch (zero-init; pad regions never written -> stay zero)
// ---------------------------------------------------------------------------
__device__ float g_A[Ldim * HP];
__device__ float g_B[Ldim * HP];
__device__ float g_C[Ldim * HP];
__device__ float g_attn[Ldim];
__device__ float g_sW3p[HP];
__device__ float g_sb2p[HP];
__device__ float g_aW3p[HP];
__device__ float g_ab2p[HP];

// bf16 hi/lo triplet buffers.  A-side slot pattern: [xh, xl, xh]
//                              B-side slot pattern: [bh, bh, bl]
__device__ __align__(16) __nv_bfloat16 g_Ss[(size_t)Ldim * 3072];
__device__ __align__(16) __nv_bfloat16 g_Es[(size_t)Ldim * 1536];
__device__ __align__(16) __nv_bfloat16 g_H1s[(size_t)Ldim * 480];
__device__ __align__(16) __nv_bfloat16 g_Xs[(size_t)TP * 480];
__device__ __align__(16) __nv_bfloat16 g_W1s[3 * 160 * 3072];
__device__ __align__(16) __nv_bfloat16 g_WCs[160 * 1536];
__device__ __align__(16) __nv_bfloat16 g_Wl2s[160 * 480];
__device__ __align__(16) __nv_bfloat16 g_W2s[160 * 480];

// ---------------------------------------------------------------------------
// Combined split kernel: activations + all weights + padded vectors
// ---------------------------------------------------------------------------
__global__ void split_all(const float* __restrict__ states,
                          const float* __restrict__ embeds,
                          const float* __restrict__ sW1,
                          const float* __restrict__ aW1,
                          const float* __restrict__ aW2,
                          const float* __restrict__ sW2,
                          const float* __restrict__ sW3,
                          const float* __restrict__ sb2,
                          const float* __restrict__ aW3,
                          const float* __restrict__ ab2)
{
    int idx = blockIdx.x * 256 + threadIdx.x;
    const int NS = Ldim * 128;          // state k-groups
    const int NE = Ldim * 64;           // embed k-groups

    if (idx < NS + NE) {                // ---- activations (A-side pattern) ----
        const float* src;
        __nv_bfloat16* dst;
        int kg;
        if (idx < NS) {
            int row = idx >> 7; kg = idx & 127;
            src = states + (size_t)row * Sdim;
            dst = g_Ss + (size_t)row * 3072;
        } else {
            int r2 = idx - NS;
            int row = r2 >> 6; kg = r2 & 63;
            src = embeds + (size_t)row * Edim;
            dst = g_Es + (size_t)row * 1536;
        }
        float4 v0 = *(const float4*)(src + kg * 8);
        float4 v1 = *(const float4*)(src + kg * 8 + 4);
        float e[8] = {v0.x, v0.y, v0.z, v0.w, v1.x, v1.y, v1.z, v1.w};
        __align__(16) __nv_bfloat16 t[24];
#pragma unroll
        for (int q = 0; q < 8; q++) {
            __nv_bfloat16 h = __float2bfloat16(e[q]);
            __nv_bfloat16 l = __float2bfloat16(e[q] - __bfloat162float(h));
            t[3 * q] = h; t[3 * q + 1] = l; t[3 * q + 2] = h;
        }
        uint4* d4 = (uint4*)(dst + kg * 24);
        const uint4* s4 = (const uint4*)t;
        d4[0] = s4[0]; d4[1] = s4[1]; d4[2] = s4[2];
        return;
    }
    idx -= NS + NE;                     // ---- weights (B-side pattern) ----

    float e[8];
    __nv_bfloat16* dst;
    if (idx < 61440) {                  // g_W1s: 3 tiles, K=1024
        int t = idx / 20480, r = idx % 20480;
        int kg = r / 160, n = r % 160;
#pragma unroll
        for (int q = 0; q < 8; q++) {
            int k = kg * 8 + q;
            float v = 0.f;
            if (n < Hdim)
                v = (t == 0) ? sW1[(size_t)k * Hdim + n]
                  : (t == 1) ? sW1[(size_t)(1024 + k) * Hdim + n]
                             : aW1[(size_t)k * Hdim + n];
            e[q] = v;
        }
        dst = g_W1s + ((size_t)t * 160 + n) * 3072 + kg * 24;
    } else if (idx < 71680) {           // g_WCs: K=512
        int r = idx - 61440;
        int kg = r / 160, n = r % 160;
#pragma unroll
        for (int q = 0; q < 8; q++) {
            int k = kg * 8 + q;
            e[q] = (n < Hdim) ? sW1[(size_t)(2048 + k) * Hdim + n] : 0.f;
        }
        dst = g_WCs + (size_t)n * 1536 + kg * 24;
    } else if (idx < 74880) {           // g_Wl2s
        int r = idx - 71680;
        int kg = r / 160, n = r % 160;
#pragma unroll
        for (int q = 0; q < 8; q++) {
            int k = kg * 8 + q;
            e[q] = (n < Hdim && k < Hdim) ? aW2[(size_t)k * Hdim + n] : 0.f;
        }
        dst = g_Wl2s + (size_t)n * 480 + kg * 24;
    } else if (idx < 78080) {           // g_W2s
        int r = idx - 74880;
        int kg = r / 160, n = r % 160;
#pragma unroll
        for (int q = 0; q < 8; q++) {
            int k = kg * 8 + q;
            e[q] = (n < Hdim && k < Hdim) ? sW2[(size_t)k * Hdim + n] : 0.f;
        }
        dst = g_W2s + (size_t)n * 480 + kg * 24;
    } else if (idx < 78240) {
        int c = idx - 78080;
        g_sW3p[c] = (c < Hdim) ? sW3[c] : 0.f;
        g_sb2p[c] = (c < Hdim) ? sb2[c] : 0.f;
        return;
    } else if (idx < 78400) {
        int c = idx - 78240;
        g_aW3p[c] = (c < Hdim) ? aW3[c] : 0.f;
        g_ab2p[c] = (c < Hdim) ? ab2[c] : 0.f;
        return;
    } else return;

    __align__(16) __nv_bfloat16 t24[24];
#pragma unroll
    for (int q = 0; q < 8; q++) {
        __nv_bfloat16 h = __float2bfloat16(e[q]);
        __nv_bfloat16 l = __float2bfloat16(e[q] - __bfloat162float(h));
        t24[3 * q] = h; t24[3 * q + 1] = h; t24[3 * q + 2] = l;
    }
    uint4* d4 = (uint4*)dst;
    const uint4* s4 = (const uint4*)t24;
    d4[0] = s4[0]; d4[1] = s4[1]; d4[2] = s4[2];
}

// ---------------------------------------------------------------------------
// Tensor-core GEMM, templated block height BM = 32*MI, 320 threads = 10 warps
// (2m x 5n), warp tile (16*MI) x 32. mma m16n8k16 bf16, hi/lo K-triplets.
// modes: 0 = fp32 store, 2 = fused vec-dot epilogue, 3 = bias+relu -> triplets
// jobs:  0 = precompute (grid.y: A,B,H1-triplets,C), 2 = l2+l3 -> g_attn,
//        3 = big GEMM + layer3 -> out
// ---------------------------------------------------------------------------
template<int MI, int MINB>
__global__ __launch_bounds__(320, MINB)
void mma_main(int job, const float* __restrict__ bias,
              const float* __restrict__ sc, float* __restrict__ outv)
{
    constexpr int BMt = 32 * MI;
    constexpr int NA  = (BMt * 6 + 319) / 320;
    extern __shared__ char smx[];
    __nv_bfloat16* Ab[2] = {(__nv_bfloat16*)smx,
                            (__nv_bfloat16*)smx + BMt * 56};
    __nv_bfloat16* Bb[2] = {(__nv_bfloat16*)smx + 2 * BMt * 56,
                            (__nv_bfloat16*)smx + 2 * BMt * 56 + 8960};
    float* red = (float*)(smx + (2 * BMt * 56 + 17920) * 2);

    // job config
    const __nv_bfloat16 *Asrc, *Wsrc;
    int Kp, nch, mode, Tmax = 0;
    float* dst = nullptr;
    const float *wvec = nullptr, *bvec = nullptr;
    if (job == 0) {
        int y = blockIdx.y;
        if (y < 3) {
            Asrc = g_Ss; Kp = 3072; nch = 64;
            Wsrc = g_W1s + (size_t)y * 160 * 3072;
            if (y == 0)      { dst = g_A; mode = 0; }
            else if (y == 1) { dst = g_B; mode = 0; }
            else             { mode = 3; }
        } else {
            Asrc = g_Es; Kp = 1536; nch = 32; Wsrc = g_WCs; dst = g_C; mode = 0;
        }
    } else if (job == 2) {
        Asrc = g_H1s; Kp = 480; nch = 10; Wsrc = g_Wl2s; mode = 2;
        wvec = g_aW3p; bvec = g_ab2p; dst = g_attn; Tmax = Ldim;
    } else {
        Asrc = g_Xs; Kp = 480; nch = 10; Wsrc = g_W2s; mode = 2;
        wvec = g_sW3p; bvec = g_sb2p; dst = outv; Tmax = Ttot;
    }

    const int tid  = threadIdx.x;
    const int lane = tid & 31;
    const int w    = tid >> 5;
    const int wm   = w / 5;
    const int wn   = w % 5;
    const int g    = lane >> 2;
    const int tg   = lane & 3;
    const int row0 = blockIdx.x * BMt;
    const int abase = (wm * 16 * MI + g) * 28 + tg;
    const int bbase = (wn * 32 + g) * 28 + tg;

    float acc[MI][4][4];
#pragma unroll
    for (int i = 0; i < MI; i++)
#pragma unroll
        for (int j = 0; j < 4; j++)
#pragma unroll
            for (int k = 0; k < 4; k++) acc[i][j][k] = 0.f;

    uint4 rA[NA], rB[3];

    auto loadAB = [&](int ch) {
        int c48 = ch * 48;
#pragma unroll
        for (int it = 0; it < NA; it++) {
            int idx = tid + it * 320;
            if (idx < BMt * 6) {
                int m = idx / 6, q = idx - 6 * m;
                rA[it] = *(const uint4*)(Asrc + (size_t)(row0 + m) * Kp + c48 + q * 8);
            }
        }
#pragma unroll
        for (int it = 0; it < 3; it++) {
            int idx = tid + it * 320;
            int n = idx / 6, q = idx - 6 * n;
            rB[it] = *(const uint4*)(Wsrc + (size_t)n * Kp + c48 + q * 8);
        }
    };
    auto storeAB = [&](int pp) {
#pragma unroll
        for (int it = 0; it < NA; it++) {
            int idx = tid + it * 320;
            if (idx < BMt * 6) {
                int m = idx / 6, q = idx - 6 * m;
                *(uint4*)(Ab[pp] + m * 56 + q * 8) = rA[it];
            }
        }
#pragma unroll
        for (int it = 0; it < 3; it++) {
            int idx = tid + it * 320;
            int n = idx / 6, q = idx - 6 * n;
            *(uint4*)(Bb[pp] + n * 56 + q * 8) = rB[it];
        }
    };
    auto domma = [&](int pp) {
        const unsigned* As32 = (const unsigned*)Ab[pp];
        const unsigned* Bs32 = (const unsigned*)Bb[pp];
#pragma unroll
        for (int st = 0; st < 3; st++) {
            const int ko = st * 8;
            unsigned b0[4], b1[4];
#pragma unroll
            for (int j = 0; j < 4; j++) {
                b0[j] = Bs32[bbase + j * 224 + ko];
                b1[j] = Bs32[bbase + j * 224 + ko + 4];
            }
#pragma unroll
            for (int i = 0; i < MI; i++) {
                unsigned a0 = As32[abase + i * 448 + ko];
                unsigned a1 = As32[abase + i * 448 + 224 + ko];
                unsigned a2 = As32[abase + i * 448 + ko + 4];
                unsigned a3 = As32[abase + i * 448 + 224 + ko + 4];
#pragma unroll
                for (int j = 0; j < 4; j++) {
                    asm volatile(
                        "mma.sync.aligned.m16n8k16.row.col.f32.bf16.bf16.f32 "
                        "{%0,%1,%2,%3},{%4,%5,%6,%7},{%8,%9},{%0,%1,%2,%3};"
                        : "+f"(acc[i][j][0]), "+f"(acc[i][j][1]),
                          "+f"(acc[i][j][2]), "+f"(acc[i][j][3])
                        : "r"(a0), "r"(a1), "r"(a2), "r"(a3),
                          "r"(b0[j]), "r"(b1[j]));
                }
            }
        }
    };

    loadAB(0);
    storeAB(0);
    __syncthreads();
    int p = 0;
    for (int ch = 0; ch < nch; ch++) {
        bool more = (ch + 1 < nch);
        if (more) loadAB(ch + 1);
        domma(p);
        __syncthreads();
        if (more) { storeAB(p ^ 1); __syncthreads(); }
        p ^= 1;
    }

    if (mode == 0) {
#pragma unroll
        for (int i = 0; i < MI; i++) {
            int r = row0 + wm * 16 * MI + i * 16 + g;
#pragma unroll
            for (int j = 0; j < 4; j++) {
                int c = wn * 32 + j * 8 + 2 * tg;
                if (c < Hdim) {
                    dst[(size_t)r * HP + c]           = acc[i][j][0];
                    dst[(size_t)r * HP + c + 1]       = acc[i][j][1];
                    dst[(size_t)(r + 8) * HP + c]     = acc[i][j][2];
                    dst[(size_t)(r + 8) * HP + c + 1] = acc[i][j][3];
                }
            }
        }
    } else if (mode == 3) {
#pragma unroll
        for (int i = 0; i < MI; i++) {
            int r = row0 + wm * 16 * MI + i * 16 + g;
#pragma unroll
            for (int j = 0; j < 4; j++) {
                int c = wn * 32 + j * 8 + 2 * tg;
                if (c < Hdim) {
                    float b0 = bias[c], b1 = bias[c + 1];
                    float v0 = fmaxf(acc[i][j][0] + b0, 0.f);
                    float v1 = fmaxf(acc[i][j][1] + b1, 0.f);
                    float v2 = fmaxf(acc[i][j][2] + b0, 0.f);
                    float v3 = fmaxf(acc[i][j][3] + b1, 0.f);
#pragma unroll
                    for (int hh = 0; hh < 2; hh++) {
                        float va = hh ? v2 : v0, vb = hh ? v3 : v1;
                        int rr = r + 8 * hh;
                        __nv_bfloat16 ha = __float2bfloat16(va);
                        __nv_bfloat16 la = __float2bfloat16(va - __bfloat162float(ha));
                        __nv_bfloat16 hb = __float2bfloat16(vb);
                        __nv_bfloat16 lb = __float2bfloat16(vb - __bfloat162float(hb));
                        __nv_bfloat162* pt =
                            (__nv_bfloat162*)(g_H1s + (size_t)rr * 480 + 3 * c);
                        pt[0] = __nv_bfloat162{ha, la};
                        pt[1] = __nv_bfloat162{ha, hb};
                        pt[2] = __nv_bfloat162{lb, hb};
                    }
                }
            }
        }
    } else {
#pragma unroll
        for (int i = 0; i < MI; i++) {
            float pl = 0.f, ph = 0.f;
#pragma unroll
            for (int j = 0; j < 4; j++) {
                int c = wn * 32 + j * 8 + 2 * tg;
                float w0 = wvec[c], w1 = wvec[c + 1];
                float s0 = bvec[c], s1 = bvec[c + 1];
                pl += w0 * fmaxf(acc[i][j][0] + s0, 0.f)
                    + w1 * fmaxf(acc[i][j][1] + s1, 0.f);
                ph += w0 * fmaxf(acc[i][j][2] + s0, 0.f)
                    + w1 * fmaxf(acc[i][j][3] + s1, 0.f);
            }
            pl += __shfl_xor_sync(0xffffffffu, pl, 1);
            pl += __shfl_xor_sync(0xffffffffu, pl, 2);
            ph += __shfl_xor_sync(0xffffffffu, ph, 1);
            ph += __shfl_xor_sync(0xffffffffu, ph, 2);
            if (tg == 0) {
                int rl = wm * 16 * MI + i * 16 + g;
                red[rl * 5 + wn]       = pl;
                red[(rl + 8) * 5 + wn] = ph;
            }
        }
        __syncthreads();
        if (tid < BMt) {
            float s = sc[0];
#pragma unroll
            for (int q = 0; q < 5; q++) s += red[tid * 5 + q];
            int t = row0 + tid;
            if (t < Tmax) dst[t] = s;
        }
    }
}

// ---------------------------------------------------------------------------
// Pool kernel, templated on window size n (fully unrolled inner loops)
// ---------------------------------------------------------------------------
template<int N>
__device__ __forceinline__ void pool_body(const float* __restrict__ sb1,
                                          float* attw, float* wsm)
{
    const int tid = threadIdx.x;
    const int s0  = blockIdx.x * 128;
    const int M   = Ldim - N + 1;
    const int nw  = 128 + N - 1;
    const int off = (N - 1) * (Ldim + 1) - (N * (N - 1)) / 2;

    for (int idx = tid; idx < nw; idx += 256) {
        int gg = s0 + idx;
        attw[idx] = (gg < Ldim) ? g_attn[gg] : 0.f;
    }
    __syncthreads();

    if (tid < 128) {
        int r = tid;
        float mx = -1e30f;
#pragma unroll
        for (int j = 0; j < N; j++) mx = fmaxf(mx, attw[r + j]);
        float s = 0.f;
#pragma unroll
        for (int j = 0; j < N; j++) {
            float e = expf(attw[r + j] - mx);
            wsm[r * 12 + j] = e; s += e;
        }
        float inv = 1.f / s;
#pragma unroll
        for (int j = 0; j < N; j++) wsm[r * 12 + j] *= inv;
    }
    __syncthreads();

    const int warp = tid >> 5, lane = tid & 31;
#pragma unroll
    for (int rr = 0; rr < 16; rr++) {
        int r = warp + rr * 8;
        int start = s0 + r;
        if (start >= M) continue;
        float wj[N];
#pragma unroll
        for (int j = 0; j < N; j++) wj[j] = wsm[r * 12 + j];
        size_t tb = (size_t)(off + start) * 480;
        size_t ab = (size_t)start * HP;
        size_t bb = (size_t)(start + N - 1) * HP;
#pragma unroll
        for (int k = 0; k < 5; k++) {
            int c = lane + 32 * k;
            if (c < Hdim) {
                float v = g_A[ab + c] + g_B[bb + c] + sb1[c];
#pragma unroll
                for (int j = 0; j < N; j++)
                    v += wj[j] * g_C[(size_t)(start + j) * HP + c];
                v = fmaxf(v, 0.f);
                __nv_bfloat16 h = __float2bfloat16(v);
                __nv_bfloat16 l = __float2bfloat16(v - __bfloat162float(h));
                g_Xs[tb + 3 * c]     = h;
                g_Xs[tb + 3 * c + 1] = l;
                g_Xs[tb + 3 * c + 2] = h;
            }
        }
    }
}

__global__ void pool_kernel(const float* __restrict__ sb1)
{
    __shared__ float attw[140];
    __shared__ float wsm[128 * 12];
    switch (blockIdx.y) {
        case 0: pool_body<1>(sb1, attw, wsm); break;
        case 1: pool_body<2>(sb1, attw, wsm); break;
        case 2: pool_body<3>(sb1, attw, wsm); break;
        case 3: pool_body<4>(sb1, attw, wsm); break;
        case 4: pool_body<5>(sb1, attw, wsm); break;
        case 5: pool_body<6>(sb1, attw, wsm); break;
        case 6: pool_body<7>(sb1, attw, wsm); break;
        case 7: pool_body<8>(sb1, attw, wsm); break;
        case 8: pool_body<9>(sb1, attw, wsm); break;
        default: pool_body<10>(sb1, attw, wsm); break;
    }
}

// ---------------------------------------------------------------------------
extern "C" void kernel_launch(void* const* d_in, const int* in_sizes, int n_in,
                              void* d_out, int out_size)
{
    const float* embeds = (const float*)d_in[0];
    const float* states = (const float*)d_in[1];
    const float* aW1    = (const float*)d_in[2];
    const float* ab1    = (const float*)d_in[3];
    const float* aW2    = (const float*)d_in[4];
    const float* ab2    = (const float*)d_in[5];
    const float* aW3    = (const float*)d_in[6];
    const float* ab3    = (const float*)d_in[7];
    const float* sW1    = (const float*)d_in[8];
    const float* sb1    = (const float*)d_in[9];
    const float* sW2    = (const float*)d_in[10];
    const float* sb2    = (const float*)d_in[11];
    const float* sW3    = (const float*)d_in[12];
    const float* sb3    = (const float*)d_in[13];
    float* out = (float*)d_out;

    cudaFuncSetAttribute(mma_main<4, 1>,
                         cudaFuncAttributeMaxDynamicSharedMemorySize, 67072);
    cudaFuncSetAttribute(mma_main<1, 3>,
                         cudaFuncAttributeMaxDynamicSharedMemorySize, 43648);
    cudaFuncSetAttribute(mma_main<2, 2>,
                         cudaFuncAttributeMaxDynamicSharedMemorySize, 51456);

    // all splits (acts + weights + padded vectors), one launch
    split_all<<<3379, 256>>>(states, embeds, sW1, aW1, aW2, sW2,
                             sW3, sb2, aW3, ab2);
    // precompute GEMMs: g_A, g_B, H1-triplets, g_C  (one wave, BM=128)
    mma_main<4, 1><<<dim3(32, 4), 320, 67072>>>(0, ab1, nullptr, nullptr);
    // attn layer2 + layer3 fused -> g_attn  (BM=32, grid 128)
    mma_main<1, 3><<<dim3(128, 1), 320, 43648>>>(2, nullptr, ab3, nullptr);
    // pooled rows (bf16 triplets) -> g_Xs
    pool_kernel<<<dim3(32, 10), 256>>>(sb1);
    // big GEMM + fused layer3 -> out  (BM=64, grid 640)
    mma_main<2, 2><<<dim3(640, 1), 320, 51456>>>(3, nullptr, sb3, out);
}

// round 8
// speedup vs baseline: 1.6606x; 1.0099x over previous
#include <cuda_runtime.h>
#include <cuda_bf16.h>
#include <math.h>

#define Ldim 4096
#define Edim 512
#define Sdim 1024
#define Hdim 150
#define HP   160
#define MAXN 10
#define Ttot 40915
#define TP   40960

// ---------------------------------------------------------------------------
// Device scratch (zero-init; pad regions never written -> stay zero)
// ---------------------------------------------------------------------------
__device__ float g_A[Ldim * HP];
__device__ float g_B[Ldim * HP];
__device__ float g_C[Ldim * HP];
__device__ float g_attn[Ldim];
__device__ float g_sW3p[HP];
__device__ float g_sb2p[HP];
__device__ float g_aW3p[HP];
__device__ float g_ab2p[HP];

// bf16 hi/lo triplet buffers.  A-side slot pattern: [xh, xl, xh]
//                              B-side slot pattern: [bh, bh, bl]
__device__ __align__(16) __nv_bfloat16 g_Ss[(size_t)Ldim * 3072];
__device__ __align__(16) __nv_bfloat16 g_Es[(size_t)Ldim * 1536];
__device__ __align__(16) __nv_bfloat16 g_H1s[(size_t)Ldim * 480];
__device__ __align__(16) __nv_bfloat16 g_Xs[(size_t)TP * 480];
__device__ __align__(16) __nv_bfloat16 g_W1s[3 * 160 * 3072];
__device__ __align__(16) __nv_bfloat16 g_WCs[160 * 1536];
__device__ __align__(16) __nv_bfloat16 g_Wl2s[160 * 480];
__device__ __align__(16) __nv_bfloat16 g_W2s[160 * 480];

// ---------------------------------------------------------------------------
// Combined split kernel: activations + all weights + padded vectors
// ---------------------------------------------------------------------------
__global__ void split_all(const float* __restrict__ states,
                          const float* __restrict__ embeds,
                          const float* __restrict__ sW1,
                          const float* __restrict__ aW1,
                          const float* __restrict__ aW2,
                          const float* __restrict__ sW2,
                          const float* __restrict__ sW3,
                          const float* __restrict__ sb2,
                          const float* __restrict__ aW3,
                          const float* __restrict__ ab2)
{
    int idx = blockIdx.x * 256 + threadIdx.x;
    const int NS = Ldim * 128;
    const int NE = Ldim * 64;

    if (idx < NS + NE) {                // ---- activations (A-side pattern) ----
        const float* src;
        __nv_bfloat16* dst;
        int kg;
        if (idx < NS) {
            int row = idx >> 7; kg = idx & 127;
            src = states + (size_t)row * Sdim;
            dst = g_Ss + (size_t)row * 3072;
        } else {
            int r2 = idx - NS;
            int row = r2 >> 6; kg = r2 & 63;
            src = embeds + (size_t)row * Edim;
            dst = g_Es + (size_t)row * 1536;
        }
        float4 v0 = *(const float4*)(src + kg * 8);
        float4 v1 = *(const float4*)(src + kg * 8 + 4);
        float e[8] = {v0.x, v0.y, v0.z, v0.w, v1.x, v1.y, v1.z, v1.w};
        __align__(16) __nv_bfloat16 t[24];
#pragma unroll
        for (int q = 0; q < 8; q++) {
            __nv_bfloat16 h = __float2bfloat16(e[q]);
            __nv_bfloat16 l = __float2bfloat16(e[q] - __bfloat162float(h));
            t[3 * q] = h; t[3 * q + 1] = l; t[3 * q + 2] = h;
        }
        uint4* d4 = (uint4*)(dst + kg * 24);
        const uint4* s4 = (const uint4*)t;
        d4[0] = s4[0]; d4[1] = s4[1]; d4[2] = s4[2];
        return;
    }
    idx -= NS + NE;                     // ---- weights (B-side pattern) ----

    float e[8];
    __nv_bfloat16* dst;
    if (idx < 61440) {                  // g_W1s: 3 tiles, K=1024
        int t = idx / 20480, r = idx % 20480;
        int kg = r / 160, n = r % 160;
#pragma unroll
        for (int q = 0; q < 8; q++) {
            int k = kg * 8 + q;
            float v = 0.f;
            if (n < Hdim)
                v = (t == 0) ? sW1[(size_t)k * Hdim + n]
                  : (t == 1) ? sW1[(size_t)(1024 + k) * Hdim + n]
                             : aW1[(size_t)k * Hdim + n];
            e[q] = v;
        }
        dst = g_W1s + ((size_t)t * 160 + n) * 3072 + kg * 24;
    } else if (idx < 71680) {           // g_WCs: K=512
        int r = idx - 61440;
        int kg = r / 160, n = r % 160;
#pragma unroll
        for (int q = 0; q < 8; q++) {
            int k = kg * 8 + q;
            e[q] = (n < Hdim) ? sW1[(size_t)(2048 + k) * Hdim + n] : 0.f;
        }
        dst = g_WCs + (size_t)n * 1536 + kg * 24;
    } else if (idx < 74880) {           // g_Wl2s
        int r = idx - 71680;
        int kg = r / 160, n = r % 160;
#pragma unroll
        for (int q = 0; q < 8; q++) {
            int k = kg * 8 + q;
            e[q] = (n < Hdim && k < Hdim) ? aW2[(size_t)k * Hdim + n] : 0.f;
        }
        dst = g_Wl2s + (size_t)n * 480 + kg * 24;
    } else if (idx < 78080) {           // g_W2s
        int r = idx - 74880;
        int kg = r / 160, n = r % 160;
#pragma unroll
        for (int q = 0; q < 8; q++) {
            int k = kg * 8 + q;
            e[q] = (n < Hdim && k < Hdim) ? sW2[(size_t)k * Hdim + n] : 0.f;
        }
        dst = g_W2s + (size_t)n * 480 + kg * 24;
    } else if (idx < 78240) {
        int c = idx - 78080;
        g_sW3p[c] = (c < Hdim) ? sW3[c] : 0.f;
        g_sb2p[c] = (c < Hdim) ? sb2[c] : 0.f;
        return;
    } else if (idx < 78400) {
        int c = idx - 78240;
        g_aW3p[c] = (c < Hdim) ? aW3[c] : 0.f;
        g_ab2p[c] = (c < Hdim) ? ab2[c] : 0.f;
        return;
    } else return;

    __align__(16) __nv_bfloat16 t24[24];
#pragma unroll
    for (int q = 0; q < 8; q++) {
        __nv_bfloat16 h = __float2bfloat16(e[q]);
        __nv_bfloat16 l = __float2bfloat16(e[q] - __bfloat162float(h));
        t24[3 * q] = h; t24[3 * q + 1] = h; t24[3 * q + 2] = l;
    }
    uint4* d4 = (uint4*)dst;
    const uint4* s4 = (const uint4*)t24;
    d4[0] = s4[0]; d4[1] = s4[1]; d4[2] = s4[2];
}

// ---------------------------------------------------------------------------
// Tensor-core GEMM (unchanged math/layout). Templated BM = 32*MI.
// ---------------------------------------------------------------------------
template<int MI, int MINB>
__global__ __launch_bounds__(320, MINB)
void mma_main(int job, const float* __restrict__ bias,
              const float* __restrict__ sc, float* __restrict__ outv)
{
    constexpr int BMt = 32 * MI;
    constexpr int NA  = (BMt * 6 + 319) / 320;
    extern __shared__ char smx[];
    __nv_bfloat16* Ab[2] = {(__nv_bfloat16*)smx,
                            (__nv_bfloat16*)smx + BMt * 56};
    __nv_bfloat16* Bb[2] = {(__nv_bfloat16*)smx + 2 * BMt * 56,
                            (__nv_bfloat16*)smx + 2 * BMt * 56 + 8960};
    float* red = (float*)(smx + (2 * BMt * 56 + 17920) * 2);

    const __nv_bfloat16 *Asrc, *Wsrc;
    int Kp, nch, mode, Tmax = 0;
    float* dst = nullptr;
    const float *wvec = nullptr, *bvec = nullptr;
    if (job == 0) {
        int y = blockIdx.y;
        if (y < 3) {
            Asrc = g_Ss; Kp = 3072; nch = 64;
            Wsrc = g_W1s + (size_t)y * 160 * 3072;
            if (y == 0)      { dst = g_A; mode = 0; }
            else if (y == 1) { dst = g_B; mode = 0; }
            else             { mode = 3; }
        } else {
            Asrc = g_Es; Kp = 1536; nch = 32; Wsrc = g_WCs; dst = g_C; mode = 0;
        }
    } else if (job == 2) {
        Asrc = g_H1s; Kp = 480; nch = 10; Wsrc = g_Wl2s; mode = 2;
        wvec = g_aW3p; bvec = g_ab2p; dst = g_attn; Tmax = Ldim;
    } else {
        Asrc = g_Xs; Kp = 480; nch = 10; Wsrc = g_W2s; mode = 2;
        wvec = g_sW3p; bvec = g_sb2p; dst = outv; Tmax = Ttot;
    }

    const int tid  = threadIdx.x;
    const int lane = tid & 31;
    const int w    = tid >> 5;
    const int wm   = w / 5;
    const int wn   = w % 5;
    const int g    = lane >> 2;
    const int tg   = lane & 3;
    const int row0 = blockIdx.x * BMt;
    const int abase = (wm * 16 * MI + g) * 28 + tg;
    const int bbase = (wn * 32 + g) * 28 + tg;

    float acc[MI][4][4];
#pragma unroll
    for (int i = 0; i < MI; i++)
#pragma unroll
        for (int j = 0; j < 4; j++)
#pragma unroll
            for (int k = 0; k < 4; k++) acc[i][j][k] = 0.f;

    uint4 rA[NA], rB[3];

    auto loadAB = [&](int ch) {
        int c48 = ch * 48;
#pragma unroll
        for (int it = 0; it < NA; it++) {
            int idx = tid + it * 320;
            if (idx < BMt * 6) {
                int m = idx / 6, q = idx - 6 * m;
                rA[it] = *(const uint4*)(Asrc + (size_t)(row0 + m) * Kp + c48 + q * 8);
            }
        }
#pragma unroll
        for (int it = 0; it < 3; it++) {
            int idx = tid + it * 320;
            int n = idx / 6, q = idx - 6 * n;
            rB[it] = *(const uint4*)(Wsrc + (size_t)n * Kp + c48 + q * 8);
        }
    };
    auto storeAB = [&](int pp) {
#pragma unroll
        for (int it = 0; it < NA; it++) {
            int idx = tid + it * 320;
            if (idx < BMt * 6) {
                int m = idx / 6, q = idx - 6 * m;
                *(uint4*)(Ab[pp] + m * 56 + q * 8) = rA[it];
            }
        }
#pragma unroll
        for (int it = 0; it < 3; it++) {
            int idx = tid + it * 320;
            int n = idx / 6, q = idx - 6 * n;
            *(uint4*)(Bb[pp] + n * 56 + q * 8) = rB[it];
        }
    };
    auto domma = [&](int pp) {
        const unsigned* As32 = (const unsigned*)Ab[pp];
        const unsigned* Bs32 = (const unsigned*)Bb[pp];
#pragma unroll
        for (int st = 0; st < 3; st++) {
            const int ko = st * 8;
            unsigned b0[4], b1[4];
#pragma unroll
            for (int j = 0; j < 4; j++) {
                b0[j] = Bs32[bbase + j * 224 + ko];
                b1[j] = Bs32[bbase + j * 224 + ko + 4];
            }
#pragma unroll
            for (int i = 0; i < MI; i++) {
                unsigned a0 = As32[abase + i * 448 + ko];
                unsigned a1 = As32[abase + i * 448 + 224 + ko];
                unsigned a2 = As32[abase + i * 448 + ko + 4];
                unsigned a3 = As32[abase + i * 448 + 224 + ko + 4];
#pragma unroll
                for (int j = 0; j < 4; j++) {
                    asm volatile(
                        "mma.sync.aligned.m16n8k16.row.col.f32.bf16.bf16.f32 "
                        "{%0,%1,%2,%3},{%4,%5,%6,%7},{%8,%9},{%0,%1,%2,%3};"
                        : "+f"(acc[i][j][0]), "+f"(acc[i][j][1]),
                          "+f"(acc[i][j][2]), "+f"(acc[i][j][3])
                        : "r"(a0), "r"(a1), "r"(a2), "r"(a3),
                          "r"(b0[j]), "r"(b1[j]));
                }
            }
        }
    };

    loadAB(0);
    storeAB(0);
    __syncthreads();
    int p = 0;
    for (int ch = 0; ch < nch; ch++) {
        bool more = (ch + 1 < nch);
        if (more) loadAB(ch + 1);
        domma(p);
        __syncthreads();
        if (more) { storeAB(p ^ 1); __syncthreads(); }
        p ^= 1;
    }

    if (mode == 0) {
#pragma unroll
        for (int i = 0; i < MI; i++) {
            int r = row0 + wm * 16 * MI + i * 16 + g;
#pragma unroll
            for (int j = 0; j < 4; j++) {
                int c = wn * 32 + j * 8 + 2 * tg;
                if (c < Hdim) {
                    dst[(size_t)r * HP + c]           = acc[i][j][0];
                    dst[(size_t)r * HP + c + 1]       = acc[i][j][1];
                    dst[(size_t)(r + 8) * HP + c]     = acc[i][j][2];
                    dst[(size_t)(r + 8) * HP + c + 1] = acc[i][j][3];
                }
            }
        }
    } else if (mode == 3) {
#pragma unroll
        for (int i = 0; i < MI; i++) {
            int r = row0 + wm * 16 * MI + i * 16 + g;
#pragma unroll
            for (int j = 0; j < 4; j++) {
                int c = wn * 32 + j * 8 + 2 * tg;
                if (c < Hdim) {
                    float b0 = bias[c], b1 = bias[c + 1];
                    float v0 = fmaxf(acc[i][j][0] + b0, 0.f);
                    float v1 = fmaxf(acc[i][j][1] + b1, 0.f);
                    float v2 = fmaxf(acc[i][j][2] + b0, 0.f);
                    float v3 = fmaxf(acc[i][j][3] + b1, 0.f);
#pragma unroll
                    for (int hh = 0; hh < 2; hh++) {
                        float va = hh ? v2 : v0, vb = hh ? v3 : v1;
                        int rr = r + 8 * hh;
                        __nv_bfloat16 ha = __float2bfloat16(va);
                        __nv_bfloat16 la = __float2bfloat16(va - __bfloat162float(ha));
                        __nv_bfloat16 hb = __float2bfloat16(vb);
                        __nv_bfloat16 lb = __float2bfloat16(vb - __bfloat162float(hb));
                        __nv_bfloat162* pt =
                            (__nv_bfloat162*)(g_H1s + (size_t)rr * 480 + 3 * c);
                        pt[0] = __nv_bfloat162{ha, la};
                        pt[1] = __nv_bfloat162{ha, hb};
                        pt[2] = __nv_bfloat162{lb, hb};
                    }
                }
            }
        }
    } else {
#pragma unroll
        for (int i = 0; i < MI; i++) {
            float pl = 0.f, ph = 0.f;
#pragma unroll
            for (int j = 0; j < 4; j++) {
                int c = wn * 32 + j * 8 + 2 * tg;
                float w0 = wvec[c], w1 = wvec[c + 1];
                float s0 = bvec[c], s1 = bvec[c + 1];
                pl += w0 * fmaxf(acc[i][j][0] + s0, 0.f)
                    + w1 * fmaxf(acc[i][j][1] + s1, 0.f);
                ph += w0 * fmaxf(acc[i][j][2] + s0, 0.f)
                    + w1 * fmaxf(acc[i][j][3] + s1, 0.f);
            }
            pl += __shfl_xor_sync(0xffffffffu, pl, 1);
            pl += __shfl_xor_sync(0xffffffffu, pl, 2);
            ph += __shfl_xor_sync(0xffffffffu, ph, 1);
            ph += __shfl_xor_sync(0xffffffffu, ph, 2);
            if (tg == 0) {
                int rl = wm * 16 * MI + i * 16 + g;
                red[rl * 5 + wn]       = pl;
                red[(rl + 8) * 5 + wn] = ph;
            }
        }
        __syncthreads();
        if (tid < BMt) {
            float s = sc[0];
#pragma unroll
            for (int q = 0; q < 5; q++) s += red[tid * 5 + q];
            int t = row0 + tid;
            if (t < Tmax) dst[t] = s;
        }
    }
}

// ---------------------------------------------------------------------------
// Pool v2: block = 16 starts x ALL 10 window sizes. A/B/C rows staged once.
// Output packed to bf16 triplets in registers, stored as coalesced uint4.
// ---------------------------------------------------------------------------
__global__ __launch_bounds__(256)
void pool_kernel(const float* __restrict__ sb1)
{
    __shared__ float As[16][152];
    __shared__ float Bs[25][152];
    __shared__ float Cs[25][152];
    __shared__ float attw[32];
    __shared__ float sb1s[160];
    __shared__ float rowbuf[8][160];

    const int tid = threadIdx.x;
    const int s0  = blockIdx.x * 16;

    if (tid < 160) sb1s[tid] = (tid < Hdim) ? sb1[tid] : 0.f;
    if (tid >= 160 && tid < 185) {
        int i = tid - 160;
        int gg = s0 + i;
        attw[i] = (gg < Ldim) ? g_attn[gg] : 0.f;
    }
    for (int i = tid; i < 16 * 38; i += 256) {
        int r = i / 38, q = i % 38;
        *(float4*)&As[r][q * 4] = *(const float4*)(g_A + (size_t)(s0 + r) * HP + q * 4);
    }
    for (int i = tid; i < 25 * 38; i += 256) {
        int r = i / 38, q = i % 38;
        int gr = s0 + r;
        float4 v = make_float4(0.f, 0.f, 0.f, 0.f);
        if (gr < Ldim) v = *(const float4*)(g_B + (size_t)gr * HP + q * 4);
        *(float4*)&Bs[r][q * 4] = v;
    }
    for (int i = tid; i < 25 * 38; i += 256) {
        int r = i / 38, q = i % 38;
        int gr = s0 + r;
        float4 v = make_float4(0.f, 0.f, 0.f, 0.f);
        if (gr < Ldim) v = *(const float4*)(g_C + (size_t)gr * HP + q * 4);
        *(float4*)&Cs[r][q * 4] = v;
    }
    __syncthreads();

    const int warp = tid >> 5, lane = tid & 31;
    for (int rowi = warp; rowi < 160; rowi += 8) {
        const int nidx  = rowi >> 4;        // 0..9
        const int n     = nidx + 1;
        const int si    = rowi & 15;
        const int start = s0 + si;
        if (start >= Ldim - n + 1) continue;    // warp-uniform

        // softmax weights (redundant per lane; n <= 10)
        float wj[MAXN];
        float mx = -1e30f;
        for (int j = 0; j < n; j++) mx = fmaxf(mx, attw[si + j]);
        float ssum = 0.f;
        for (int j = 0; j < n; j++) {
            float e = __expf(attw[si + j] - mx);
            wj[j] = e; ssum += e;
        }
        float inv = 1.f / ssum;

        // pooled h1 row (160 cols incl. zero pad)
#pragma unroll
        for (int k = 0; k < 5; k++) {
            int c = lane + 32 * k;
            float pool = 0.f;
            for (int j = 0; j < n; j++) pool += wj[j] * Cs[si + j][c];
            float v = As[si][c] + Bs[si + n - 1][c] + sb1s[c] + pool * inv;
            rowbuf[warp][c] = fmaxf(v, 0.f);
        }
        __syncwarp();

        // pack to triplets [h,l,h] and store coalesced
        const int off = (n - 1) * (Ldim + 1) - (n * (n - 1)) / 2;
        __nv_bfloat16* outp = g_Xs + (size_t)(off + start) * 480;
#pragma unroll
        for (int it = 0; it < 2; it++) {
            int ii = lane + 32 * it;
            if (ii < 60) {
                unsigned short es[8];
#pragma unroll
                for (int e = 0; e < 8; e++) {
                    int ge = ii * 8 + e;
                    int col = ge / 3, slot = ge - 3 * col;
                    float val = rowbuf[warp][col];
                    __nv_bfloat16 h = __float2bfloat16(val);
                    __nv_bfloat16 x = (slot == 1)
                        ? __float2bfloat16(val - __bfloat162float(h)) : h;
                    unsigned short us;
                    __builtin_memcpy(&us, &x, 2);
                    es[e] = us;
                }
                uint4 u;
                u.x = es[0] | ((unsigned)es[1] << 16);
                u.y = es[2] | ((unsigned)es[3] << 16);
                u.z = es[4] | ((unsigned)es[5] << 16);
                u.w = es[6] | ((unsigned)es[7] << 16);
                *(uint4*)(outp + ii * 8) = u;
            }
        }
        __syncwarp();
    }
}

// ---------------------------------------------------------------------------
extern "C" void kernel_launch(void* const* d_in, const int* in_sizes, int n_in,
                              void* d_out, int out_size)
{
    const float* embeds = (const float*)d_in[0];
    const float* states = (const float*)d_in[1];
    const float* aW1    = (const float*)d_in[2];
    const float* ab1    = (const float*)d_in[3];
    const float* aW2    = (const float*)d_in[4];
    const float* ab2    = (const float*)d_in[5];
    const float* aW3    = (const float*)d_in[6];
    const float* ab3    = (const float*)d_in[7];
    const float* sW1    = (const float*)d_in[8];
    const float* sb1    = (const float*)d_in[9];
    const float* sW2    = (const float*)d_in[10];
    const float* sb2    = (const float*)d_in[11];
    const float* sW3    = (const float*)d_in[12];
    const float* sb3    = (const float*)d_in[13];
    float* out = (float*)d_out;

    cudaFuncSetAttribute(mma_main<4, 1>,
                         cudaFuncAttributeMaxDynamicSharedMemorySize, 67072);
    cudaFuncSetAttribute(mma_main<1, 3>,
                         cudaFuncAttributeMaxDynamicSharedMemorySize, 43648);
    cudaFuncSetAttribute(mma_main<2, 2>,
                         cudaFuncAttributeMaxDynamicSharedMemorySize, 51456);

    // all splits (acts + weights + padded vectors), one launch
    split_all<<<3379, 256>>>(states, embeds, sW1, aW1, aW2, sW2,
                             sW3, sb2, aW3, ab2);
    // precompute GEMMs: g_A, g_B, H1-triplets, g_C  (one wave, BM=128)
    mma_main<4, 1><<<dim3(32, 4), 320, 67072>>>(0, ab1, nullptr, nullptr);
    // attn layer2 + layer3 fused -> g_attn  (BM=32, grid 128)
    mma_main<1, 3><<<dim3(128, 1), 320, 43648>>>(2, nullptr, ab3, nullptr);
    // pooled rows (bf16 triplets) -> g_Xs  (16 starts x all n per block)
    pool_kernel<<<256, 256>>>(sb1);
    // big GEMM + fused layer3 -> out  (BM=64, grid 640)
    mma_main<2, 2><<<dim3(640, 1), 320, 51456>>>(3, nullptr, sb3, out);
}

// round 9
// speedup vs baseline: 1.8922x; 1.1394x over previous
#include <cuda_runtime.h>
#include <cuda_bf16.h>
#include <math.h>

#define Ldim 4096
#define Edim 512
#define Sdim 1024
#define Hdim 150
#define HP   160
#define MAXN 10
#define Ttot 40915
#define TP   40960

// ---------------------------------------------------------------------------
// Device scratch (zero-init; pad regions never written -> stay zero)
// ---------------------------------------------------------------------------
__device__ float g_A[Ldim * HP];
__device__ float g_B[Ldim * HP];
__device__ float g_C[Ldim * HP];
__device__ float g_attn[Ldim];
__device__ float g_X[(size_t)TP * HP];   // pooled rows, fp32 (pad cols stay 0)
__device__ float g_sW3p[HP];
__device__ float g_sb2p[HP];
__device__ float g_aW3p[HP];
__device__ float g_ab2p[HP];

// bf16 hi/lo triplet buffers.  A-side slot pattern: [xh, xl, xh]
//                              B-side slot pattern: [bh, bh, bl]
__device__ __align__(16) __nv_bfloat16 g_Ss[(size_t)Ldim * 3072];
__device__ __align__(16) __nv_bfloat16 g_Es[(size_t)Ldim * 1536];
__device__ __align__(16) __nv_bfloat16 g_H1s[(size_t)Ldim * 480];
__device__ __align__(16) __nv_bfloat16 g_W1s[3 * 160 * 3072];
__device__ __align__(16) __nv_bfloat16 g_WCs[160 * 1536];
__device__ __align__(16) __nv_bfloat16 g_Wl2s[160 * 480];
__device__ __align__(16) __nv_bfloat16 g_W2s[160 * 480];

// ---------------------------------------------------------------------------
// Combined split kernel: activations + all weights + padded vectors
// ---------------------------------------------------------------------------
__global__ void split_all(const float* __restrict__ states,
                          const float* __restrict__ embeds,
                          const float* __restrict__ sW1,
                          const float* __restrict__ aW1,
                          const float* __restrict__ aW2,
                          const float* __restrict__ sW2,
                          const float* __restrict__ sW3,
                          const float* __restrict__ sb2,
                          const float* __restrict__ aW3,
                          const float* __restrict__ ab2)
{
    int idx = blockIdx.x * 256 + threadIdx.x;
    const int NS = Ldim * 128;
    const int NE = Ldim * 64;

    if (idx < NS + NE) {                // ---- activations (A-side pattern) ----
        const float* src;
        __nv_bfloat16* dst;
        int kg;
        if (idx < NS) {
            int row = idx >> 7; kg = idx & 127;
            src = states + (size_t)row * Sdim;
            dst = g_Ss + (size_t)row * 3072;
        } else {
            int r2 = idx - NS;
            int row = r2 >> 6; kg = r2 & 63;
            src = embeds + (size_t)row * Edim;
            dst = g_Es + (size_t)row * 1536;
        }
        float4 v0 = *(const float4*)(src + kg * 8);
        float4 v1 = *(const float4*)(src + kg * 8 + 4);
        float e[8] = {v0.x, v0.y, v0.z, v0.w, v1.x, v1.y, v1.z, v1.w};
        __align__(16) __nv_bfloat16 t[24];
#pragma unroll
        for (int q = 0; q < 8; q++) {
            __nv_bfloat16 h = __float2bfloat16(e[q]);
            __nv_bfloat16 l = __float2bfloat16(e[q] - __bfloat162float(h));
            t[3 * q] = h; t[3 * q + 1] = l; t[3 * q + 2] = h;
        }
        uint4* d4 = (uint4*)(dst + kg * 24);
        const uint4* s4 = (const uint4*)t;
        d4[0] = s4[0]; d4[1] = s4[1]; d4[2] = s4[2];
        return;
    }
    idx -= NS + NE;                     // ---- weights (B-side pattern) ----

    float e[8];
    __nv_bfloat16* dst;
    if (idx < 61440) {                  // g_W1s: 3 tiles, K=1024
        int t = idx / 20480, r = idx % 20480;
        int kg = r / 160, n = r % 160;
#pragma unroll
        for (int q = 0; q < 8; q++) {
            int k = kg * 8 + q;
            float v = 0.f;
            if (n < Hdim)
                v = (t == 0) ? sW1[(size_t)k * Hdim + n]
                  : (t == 1) ? sW1[(size_t)(1024 + k) * Hdim + n]
                             : aW1[(size_t)k * Hdim + n];
            e[q] = v;
        }
        dst = g_W1s + ((size_t)t * 160 + n) * 3072 + kg * 24;
    } else if (idx < 71680) {           // g_WCs: K=512
        int r = idx - 61440;
        int kg = r / 160, n = r % 160;
#pragma unroll
        for (int q = 0; q < 8; q++) {
            int k = kg * 8 + q;
            e[q] = (n < Hdim) ? sW1[(size_t)(2048 + k) * Hdim + n] : 0.f;
        }
        dst = g_WCs + (size_t)n * 1536 + kg * 24;
    } else if (idx < 74880) {           // g_Wl2s
        int r = idx - 71680;
        int kg = r / 160, n = r % 160;
#pragma unroll
        for (int q = 0; q < 8; q++) {
            int k = kg * 8 + q;
            e[q] = (n < Hdim && k < Hdim) ? aW2[(size_t)k * Hdim + n] : 0.f;
        }
        dst = g_Wl2s + (size_t)n * 480 + kg * 24;
    } else if (idx < 78080) {           // g_W2s
        int r = idx - 74880;
        int kg = r / 160, n = r % 160;
#pragma unroll
        for (int q = 0; q < 8; q++) {
            int k = kg * 8 + q;
            e[q] = (n < Hdim && k < Hdim) ? sW2[(size_t)k * Hdim + n] : 0.f;
        }
        dst = g_W2s + (size_t)n * 480 + kg * 24;
    } else if (idx < 78240) {
        int c = idx - 78080;
        g_sW3p[c] = (c < Hdim) ? sW3[c] : 0.f;
        g_sb2p[c] = (c < Hdim) ? sb2[c] : 0.f;
        return;
    } else if (idx < 78400) {
        int c = idx - 78240;
        g_aW3p[c] = (c < Hdim) ? aW3[c] : 0.f;
        g_ab2p[c] = (c < Hdim) ? ab2[c] : 0.f;
        return;
    } else return;

    __align__(16) __nv_bfloat16 t24[24];
#pragma unroll
    for (int q = 0; q < 8; q++) {
        __nv_bfloat16 h = __float2bfloat16(e[q]);
        __nv_bfloat16 l = __float2bfloat16(e[q] - __bfloat162float(h));
        t24[3 * q] = h; t24[3 * q + 1] = h; t24[3 * q + 2] = l;
    }
    uint4* d4 = (uint4*)dst;
    const uint4* s4 = (const uint4*)t24;
    d4[0] = s4[0]; d4[1] = s4[1]; d4[2] = s4[2];
}

// ---------------------------------------------------------------------------
// Tensor-core GEMM. Templated BM = 32*MI. 320 threads = 10 warps (2m x 5n).
// job 3 reads A as fp32 (g_X) and converts to triplets during smem staging.
// ---------------------------------------------------------------------------
template<int MI, int MINB>
__global__ __launch_bounds__(320, MINB)
void mma_main(int job, const float* __restrict__ bias,
              const float* __restrict__ sc, float* __restrict__ outv)
{
    constexpr int BMt = 32 * MI;
    constexpr int NA  = (BMt * 6 + 319) / 320;
    extern __shared__ char smx[];
    __nv_bfloat16* Ab[2] = {(__nv_bfloat16*)smx,
                            (__nv_bfloat16*)smx + BMt * 56};
    __nv_bfloat16* Bb[2] = {(__nv_bfloat16*)smx + 2 * BMt * 56,
                            (__nv_bfloat16*)smx + 2 * BMt * 56 + 8960};
    float* red = (float*)(smx + (2 * BMt * 56 + 17920) * 2);

    const __nv_bfloat16 *Asrc = nullptr, *Wsrc;
    int Kp, nch, mode, Tmax = 0;
    bool a32 = false;
    float* dst = nullptr;
    const float *wvec = nullptr, *bvec = nullptr;
    if (job == 0) {
        int y = blockIdx.y;
        if (y < 3) {
            Asrc = g_Ss; Kp = 3072; nch = 64;
            Wsrc = g_W1s + (size_t)y * 160 * 3072;
            if (y == 0)      { dst = g_A; mode = 0; }
            else if (y == 1) { dst = g_B; mode = 0; }
            else             { mode = 3; }
        } else {
            Asrc = g_Es; Kp = 1536; nch = 32; Wsrc = g_WCs; dst = g_C; mode = 0;
        }
    } else if (job == 2) {
        Asrc = g_H1s; Kp = 480; nch = 10; Wsrc = g_Wl2s; mode = 2;
        wvec = g_aW3p; bvec = g_ab2p; dst = g_attn; Tmax = Ldim;
    } else {
        a32 = true; Kp = 480; nch = 10; Wsrc = g_W2s; mode = 2;
        wvec = g_sW3p; bvec = g_sb2p; dst = outv; Tmax = Ttot;
    }

    const int tid  = threadIdx.x;
    const int lane = tid & 31;
    const int w    = tid >> 5;
    const int wm   = w / 5;
    const int wn   = w % 5;
    const int g    = lane >> 2;
    const int tg   = lane & 3;
    const int row0 = blockIdx.x * BMt;
    const int abase = (wm * 16 * MI + g) * 28 + tg;
    const int bbase = (wn * 32 + g) * 28 + tg;

    float acc[MI][4][4];
#pragma unroll
    for (int i = 0; i < MI; i++)
#pragma unroll
        for (int j = 0; j < 4; j++)
#pragma unroll
            for (int k = 0; k < 4; k++) acc[i][j][k] = 0.f;

    uint4 rA[NA], rB[3];
    float4 fA;

    auto loadAB = [&](int ch) {
        if (a32) {
            if (tid < BMt * 4) {
                int m = tid >> 2, q = tid & 3;
                fA = *(const float4*)(g_X + (size_t)(row0 + m) * HP + ch * 16 + q * 4);
            }
        } else {
#pragma unroll
            for (int it = 0; it < NA; it++) {
                int idx = tid + it * 320;
                if (idx < BMt * 6) {
                    int m = idx / 6, q = idx - 6 * m;
                    rA[it] = *(const uint4*)(Asrc + (size_t)(row0 + m) * Kp + ch * 48 + q * 8);
                }
            }
        }
#pragma unroll
        for (int it = 0; it < 3; it++) {
            int idx = tid + it * 320;
            int n = idx / 6, q = idx - 6 * n;
            rB[it] = *(const uint4*)(Wsrc + (size_t)n * Kp + ch * 48 + q * 8);
        }
    };
    auto storeAB = [&](int pp) {
        if (a32) {
            if (tid < BMt * 4) {
                int m = tid >> 2, q = tid & 3;
                float e[4] = {fA.x, fA.y, fA.z, fA.w};
                __align__(8) __nv_bfloat16 t[12];
#pragma unroll
                for (int i2 = 0; i2 < 4; i2++) {
                    __nv_bfloat16 h = __float2bfloat16(e[i2]);
                    __nv_bfloat16 l = __float2bfloat16(e[i2] - __bfloat162float(h));
                    t[3 * i2] = h; t[3 * i2 + 1] = l; t[3 * i2 + 2] = h;
                }
                uint2* d = (uint2*)(Ab[pp] + m * 56 + q * 12);
                const uint2* s = (const uint2*)t;
                d[0] = s[0]; d[1] = s[1]; d[2] = s[2];
            }
        } else {
#pragma unroll
            for (int it = 0; it < NA; it++) {
                int idx = tid + it * 320;
                if (idx < BMt * 6) {
                    int m = idx / 6, q = idx - 6 * m;
                    *(uint4*)(Ab[pp] + m * 56 + q * 8) = rA[it];
                }
            }
        }
#pragma unroll
        for (int it = 0; it < 3; it++) {
            int idx = tid + it * 320;
            int n = idx / 6, q = idx - 6 * n;
            *(uint4*)(Bb[pp] + n * 56 + q * 8) = rB[it];
        }
    };
    auto domma = [&](int pp) {
        const unsigned* As32 = (const unsigned*)Ab[pp];
        const unsigned* Bs32 = (const unsigned*)Bb[pp];
#pragma unroll
        for (int st = 0; st < 3; st++) {
            const int ko = st * 8;
            unsigned b0[4], b1[4];
#pragma unroll
            for (int j = 0; j < 4; j++) {
                b0[j] = Bs32[bbase + j * 224 + ko];
                b1[j] = Bs32[bbase + j * 224 + ko + 4];
            }
#pragma unroll
            for (int i = 0; i < MI; i++) {
                unsigned a0 = As32[abase + i * 448 + ko];
                unsigned a1 = As32[abase + i * 448 + 224 + ko];
                unsigned a2 = As32[abase + i * 448 + ko + 4];
                unsigned a3 = As32[abase + i * 448 + 224 + ko + 4];
#pragma unroll
                for (int j = 0; j < 4; j++) {
                    asm volatile(
                        "mma.sync.aligned.m16n8k16.row.col.f32.bf16.bf16.f32 "
                        "{%0,%1,%2,%3},{%4,%5,%6,%7},{%8,%9},{%0,%1,%2,%3};"
                        : "+f"(acc[i][j][0]), "+f"(acc[i][j][1]),
                          "+f"(acc[i][j][2]), "+f"(acc[i][j][3])
                        : "r"(a0), "r"(a1), "r"(a2), "r"(a3),
                          "r"(b0[j]), "r"(b1[j]));
                }
            }
        }
    };

    loadAB(0);
    storeAB(0);
    __syncthreads();
    int p = 0;
    for (int ch = 0; ch < nch; ch++) {
        bool more = (ch + 1 < nch);
        if (more) loadAB(ch + 1);
        domma(p);
        __syncthreads();
        if (more) { storeAB(p ^ 1); __syncthreads(); }
        p ^= 1;
    }

    if (mode == 0) {
#pragma unroll
        for (int i = 0; i < MI; i++) {
            int r = row0 + wm * 16 * MI + i * 16 + g;
#pragma unroll
            for (int j = 0; j < 4; j++) {
                int c = wn * 32 + j * 8 + 2 * tg;
                if (c < Hdim) {
                    dst[(size_t)r * HP + c]           = acc[i][j][0];
                    dst[(size_t)r * HP + c + 1]       = acc[i][j][1];
                    dst[(size_t)(r + 8) * HP + c]     = acc[i][j][2];
                    dst[(size_t)(r + 8) * HP + c + 1] = acc[i][j][3];
                }
            }
        }
    } else if (mode == 3) {
#pragma unroll
        for (int i = 0; i < MI; i++) {
            int r = row0 + wm * 16 * MI + i * 16 + g;
#pragma unroll
            for (int j = 0; j < 4; j++) {
                int c = wn * 32 + j * 8 + 2 * tg;
                if (c < Hdim) {
                    float b0 = bias[c], b1 = bias[c + 1];
                    float v0 = fmaxf(acc[i][j][0] + b0, 0.f);
                    float v1 = fmaxf(acc[i][j][1] + b1, 0.f);
                    float v2 = fmaxf(acc[i][j][2] + b0, 0.f);
                    float v3 = fmaxf(acc[i][j][3] + b1, 0.f);
#pragma unroll
                    for (int hh = 0; hh < 2; hh++) {
                        float va = hh ? v2 : v0, vb = hh ? v3 : v1;
                        int rr = r + 8 * hh;
                        __nv_bfloat16 ha = __float2bfloat16(va);
                        __nv_bfloat16 la = __float2bfloat16(va - __bfloat162float(ha));
                        __nv_bfloat16 hb = __float2bfloat16(vb);
                        __nv_bfloat16 lb = __float2bfloat16(vb - __bfloat162float(hb));
                        __nv_bfloat162* pt =
                            (__nv_bfloat162*)(g_H1s + (size_t)rr * 480 + 3 * c);
                        pt[0] = __nv_bfloat162{ha, la};
                        pt[1] = __nv_bfloat162{ha, hb};
                        pt[2] = __nv_bfloat162{lb, hb};
                    }
                }
            }
        }
    } else {
#pragma unroll
        for (int i = 0; i < MI; i++) {
            float pl = 0.f, ph = 0.f;
#pragma unroll
            for (int j = 0; j < 4; j++) {
                int c = wn * 32 + j * 8 + 2 * tg;
                float w0 = wvec[c], w1 = wvec[c + 1];
                float s0 = bvec[c], s1 = bvec[c + 1];
                pl += w0 * fmaxf(acc[i][j][0] + s0, 0.f)
                    + w1 * fmaxf(acc[i][j][1] + s1, 0.f);
                ph += w0 * fmaxf(acc[i][j][2] + s0, 0.f)
                    + w1 * fmaxf(acc[i][j][3] + s1, 0.f);
            }
            pl += __shfl_xor_sync(0xffffffffu, pl, 1);
            pl += __shfl_xor_sync(0xffffffffu, pl, 2);
            ph += __shfl_xor_sync(0xffffffffu, ph, 1);
            ph += __shfl_xor_sync(0xffffffffu, ph, 2);
            if (tg == 0) {
                int rl = wm * 16 * MI + i * 16 + g;
                red[rl * 5 + wn]       = pl;
                red[(rl + 8) * 5 + wn] = ph;
            }
        }
        __syncthreads();
        if (tid < BMt) {
            float s = sc[0];
#pragma unroll
            for (int q = 0; q < 5; q++) s += red[tid * 5 + q];
            int t = row0 + tid;
            if (t < Tmax) dst[t] = s;
        }
    }
}

// ---------------------------------------------------------------------------
// Pool v3: block = 16 starts x ALL 10 n; 512 threads (16 warps, 10 rows each).
// fp32 output, direct coalesced stores. No packing, no rowbuf.
// ---------------------------------------------------------------------------
__global__ __launch_bounds__(512)
void pool_kernel(const float* __restrict__ sb1)
{
    __shared__ float As[16][152];
    __shared__ float Bs[25][152];
    __shared__ float Cs[25][152];
    __shared__ float attw[32];
    __shared__ float sb1s[160];

    const int tid = threadIdx.x;
    const int s0  = blockIdx.x * 16;

    if (tid < 160) sb1s[tid] = (tid < Hdim) ? sb1[tid] : 0.f;
    if (tid >= 160 && tid < 185) {
        int i = tid - 160;
        int gg = s0 + i;
        attw[i] = (gg < Ldim) ? g_attn[gg] : 0.f;
    }
    for (int i = tid; i < 16 * 38; i += 512) {
        int r = i / 38, q = i % 38;
        *(float4*)&As[r][q * 4] = *(const float4*)(g_A + (size_t)(s0 + r) * HP + q * 4);
    }
    for (int i = tid; i < 25 * 38; i += 512) {
        int r = i / 38, q = i % 38;
        int gr = s0 + r;
        float4 v = make_float4(0.f, 0.f, 0.f, 0.f);
        if (gr < Ldim) v = *(const float4*)(g_B + (size_t)gr * HP + q * 4);
        *(float4*)&Bs[r][q * 4] = v;
    }
    for (int i = tid; i < 25 * 38; i += 512) {
        int r = i / 38, q = i % 38;
        int gr = s0 + r;
        float4 v = make_float4(0.f, 0.f, 0.f, 0.f);
        if (gr < Ldim) v = *(const float4*)(g_C + (size_t)gr * HP + q * 4);
        *(float4*)&Cs[r][q * 4] = v;
    }
    __syncthreads();

    const int warp = tid >> 5, lane = tid & 31;
    for (int rowi = warp; rowi < 160; rowi += 16) {
        const int n     = (rowi >> 4) + 1;
        const int si    = rowi & 15;
        const int start = s0 + si;
        if (start >= Ldim - n + 1) continue;    // warp-uniform

        float wj[MAXN];
        float mx = -1e30f;
        for (int j = 0; j < n; j++) mx = fmaxf(mx, attw[si + j]);
        float ssum = 0.f;
        for (int j = 0; j < n; j++) {
            float e = __expf(attw[si + j] - mx);
            wj[j] = e; ssum += e;
        }
        float inv = 1.f / ssum;

        const int off = (n - 1) * (Ldim + 1) - (n * (n - 1)) / 2;
        float* outp = g_X + (size_t)(off + start) * HP;
#pragma unroll
        for (int k = 0; k < 5; k++) {
            int c = lane + 32 * k;
            if (c < Hdim) {
                float pool = 0.f;
                for (int j = 0; j < n; j++) pool += wj[j] * Cs[si + j][c];
                float v = As[si][c] + Bs[si + n - 1][c] + sb1s[c] + pool * inv;
                outp[c] = fmaxf(v, 0.f);
            }
        }
    }
}

// ---------------------------------------------------------------------------
extern "C" void kernel_launch(void* const* d_in, const int* in_sizes, int n_in,
                              void* d_out, int out_size)
{
    const float* embeds = (const float*)d_in[0];
    const float* states = (const float*)d_in[1];
    const float* aW1    = (const float*)d_in[2];
    const float* ab1    = (const float*)d_in[3];
    const float* aW2    = (const float*)d_in[4];
    const float* ab2    = (const float*)d_in[5];
    const float* aW3    = (const float*)d_in[6];
    const float* ab3    = (const float*)d_in[7];
    const float* sW1    = (const float*)d_in[8];
    const float* sb1    = (const float*)d_in[9];
    const float* sW2    = (const float*)d_in[10];
    const float* sb2    = (const float*)d_in[11];
    const float* sW3    = (const float*)d_in[12];
    const float* sb3    = (const float*)d_in[13];
    float* out = (float*)d_out;

    cudaFuncSetAttribute(mma_main<4, 1>,
                         cudaFuncAttributeMaxDynamicSharedMemorySize, 67072);
    cudaFuncSetAttribute(mma_main<1, 3>,
                         cudaFuncAttributeMaxDynamicSharedMemorySize, 43648);
    cudaFuncSetAttribute(mma_main<2, 2>,
                         cudaFuncAttributeMaxDynamicSharedMemorySize, 51456);

    // all splits (acts + weights + padded vectors), one launch
    split_all<<<3379, 256>>>(states, embeds, sW1, aW1, aW2, sW2,
                             sW3, sb2, aW3, ab2);
    // precompute GEMMs: g_A, g_B, H1-triplets, g_C  (one wave, BM=128)
    mma_main<4, 1><<<dim3(32, 4), 320, 67072>>>(0, ab1, nullptr, nullptr);
    // attn layer2 + layer3 fused -> g_attn  (BM=32, grid 128)
    mma_main<1, 3><<<dim3(128, 1), 320, 43648>>>(2, nullptr, ab3, nullptr);
    // pooled rows (fp32) -> g_X
    pool_kernel<<<256, 512>>>(sb1);
    // big GEMM (fp32 A staged->triplets) + fused layer3 -> out
    mma_main<2, 2><<<dim3(640, 1), 320, 51456>>>(3, nullptr, sb3, out);
}